// round 6
// baseline (speedup 1.0000x reference)
#include <cuda_runtime.h>
#include <cuda_bf16.h>
#include <cstdint>

// ---------------- problem constants ----------------
#define BATCH 2
#define S_LEN 2048
#define PREV_LEN 1024
#define T_LEN 3072
#define DIM 2048
#define HEADS 16
#define HD 128
#define FF_DIM 8192
#define ROWS (BATCH * S_LEN)  // 4096
#define QK_SCALE 0.08838834764831845f

#define OUT_X_ELEMS  (BATCH * S_LEN * DIM)
#define OUT_KV_ELEMS (BATCH * HEADS * T_LEN * HD)

// ================= PTX helpers (portable sm_80+) ====
__device__ __forceinline__ uint32_t smem_u32(const void* p) {
    uint32_t a;
    asm("{ .reg .u64 t; cvta.to.shared.u64 t, %1; cvt.u32.u64 %0, t; }" : "=r"(a) : "l"(p));
    return a;
}
__device__ __forceinline__ void cp_async16(uint32_t smem, const void* g) {
    asm volatile("cp.async.cg.shared.global [%0], [%1], 16;" :: "r"(smem), "l"(g) : "memory");
}
#define CP_COMMIT() asm volatile("cp.async.commit_group;" ::: "memory")
#define CP_WAIT2()  asm volatile("cp.async.wait_group 2;" ::: "memory")
#define CP_WAIT1()  asm volatile("cp.async.wait_group 1;" ::: "memory")

__device__ __forceinline__ void ldsm4(uint32_t* r, uint32_t addr) {
    asm volatile("ldmatrix.sync.aligned.m8n8.x4.shared.b16 {%0,%1,%2,%3}, [%4];"
        : "=r"(r[0]), "=r"(r[1]), "=r"(r[2]), "=r"(r[3]) : "r"(addr));
}
__device__ __forceinline__ void ldsm4t(uint32_t* r, uint32_t addr) {
    asm volatile("ldmatrix.sync.aligned.m8n8.x4.trans.shared.b16 {%0,%1,%2,%3}, [%4];"
        : "=r"(r[0]), "=r"(r[1]), "=r"(r[2]), "=r"(r[3]) : "r"(addr));
}
__device__ __forceinline__ void mma_bf16(float* c, const uint32_t* a, uint32_t b0, uint32_t b1) {
    asm volatile(
        "mma.sync.aligned.m16n8k16.row.col.f32.bf16.bf16.f32 "
        "{%0,%1,%2,%3}, {%4,%5,%6,%7}, {%8,%9}, {%0,%1,%2,%3};"
        : "+f"(c[0]), "+f"(c[1]), "+f"(c[2]), "+f"(c[3])
        : "r"(a[0]), "r"(a[1]), "r"(a[2]), "r"(a[3]), "r"(b0), "r"(b1));
}
__device__ __forceinline__ uint32_t pack_bf16(float a, float b) {
    __nv_bfloat162 t = __floats2bfloat162_rn(a, b);
    return *(uint32_t*)&t;
}
__device__ __forceinline__ void split_store2(
    __nv_bfloat16* Hi, __nv_bfloat16* Lo, size_t off, float a, float b)
{
    __nv_bfloat16 ha = __float2bfloat16(a), hb = __float2bfloat16(b);
    __nv_bfloat162 hh; hh.x = ha; hh.y = hb;
    __nv_bfloat162 ll;
    ll.x = __float2bfloat16(a - __bfloat162float(ha));
    ll.y = __float2bfloat16(b - __bfloat162float(hb));
    *(__nv_bfloat162*)(Hi + off) = hh;
    *(__nv_bfloat162*)(Lo + off) = ll;
}

// ---------------- scratch (device globals) --------
__device__ float g_x1 [ROWS * DIM];
__device__ float g_g  [ROWS * FF_DIM];
// bf16 hi/lo row-major activations
__device__ __nv_bfloat16 g_hA_hi [ROWS * DIM];
__device__ __nv_bfloat16 g_hA_lo [ROWS * DIM];
__device__ __nv_bfloat16 g_h2_hi [ROWS * DIM];
__device__ __nv_bfloat16 g_h2_lo [ROWS * DIM];
__device__ __nv_bfloat16 g_o_hi  [ROWS * DIM];
__device__ __nv_bfloat16 g_o_lo  [ROWS * DIM];
__device__ __nv_bfloat16 g_gt_hi [ROWS * FF_DIM];
__device__ __nv_bfloat16 g_gt_lo [ROWS * FF_DIM];
// bf16 attention operands (b,h,s/t,d)
__device__ __nv_bfloat16 g_q16h [ROWS * DIM];
__device__ __nv_bfloat16 g_q16l [ROWS * DIM];
__device__ __nv_bfloat16 g_k16h [OUT_KV_ELEMS];
__device__ __nv_bfloat16 g_k16l [OUT_KV_ELEMS];
__device__ __nv_bfloat16 g_v16  [OUT_KV_ELEMS];
// bf16 hi/lo transposed weights [N][K]
__device__ __nv_bfloat16 g_wqkv_hi[3 * DIM * DIM];
__device__ __nv_bfloat16 g_wqkv_lo[3 * DIM * DIM];
__device__ __nv_bfloat16 g_wo_hi [DIM * DIM];
__device__ __nv_bfloat16 g_wo_lo [DIM * DIM];
__device__ __nv_bfloat16 g_wg_hi [DIM * FF_DIM];
__device__ __nv_bfloat16 g_wg_lo [DIM * FF_DIM];
__device__ __nv_bfloat16 g_wv2_hi[DIM * FF_DIM];
__device__ __nv_bfloat16 g_wv2_lo[DIM * FF_DIM];
__device__ __nv_bfloat16 g_wp_hi [FF_DIM * DIM];
__device__ __nv_bfloat16 g_wp_lo [FF_DIM * DIM];

// =====================================================================
// Weight converter + transpose v2: W[K][N] fp32 -> Wt[N][K] bf16 hi/lo.
// 32(k) x 128(n) tile per block, vectorized both directions.
// grid (K/32, N/128), 256 threads.
// =====================================================================
__global__ __launch_bounds__(256) void weight_conv_t(
    const float* __restrict__ W, __nv_bfloat16* __restrict__ Thi,
    __nv_bfloat16* __restrict__ Tlo, int N, int K)
{
    __shared__ float tile[32][133];
    const int k0 = blockIdx.x * 32, n0 = blockIdx.y * 128;
    const int tid = threadIdx.x;

    // load: each thread 4 consecutive float4 (16 floats along n)
    {
        const int kr = tid >> 3;             // 0..31
        const int nq = (tid & 7) * 16;       // 0,16,..112
        const float* src = W + (size_t)(k0 + kr) * N + n0 + nq;
        #pragma unroll
        for (int u = 0; u < 4; u++) {
            float4 v = *(const float4*)(src + u * 4);
            tile[kr][nq + u * 4 + 0] = v.x;
            tile[kr][nq + u * 4 + 1] = v.y;
            tile[kr][nq + u * 4 + 2] = v.z;
            tile[kr][nq + u * 4 + 3] = v.w;
        }
    }
    __syncthreads();

    // store: each thread one n row, 16 k values as 2 x uint4 (8 bf16 each)
    const int n = tid >> 1;
    const int q = tid & 1;
    __align__(16) __nv_bfloat16 hv[16], lv[16];
    #pragma unroll
    for (int u = 0; u < 16; u++) {
        float v = tile[q * 16 + u][n];
        __nv_bfloat16 h = __float2bfloat16(v);
        hv[u] = h;
        lv[u] = __float2bfloat16(v - __bfloat162float(h));
    }
    const size_t off = (size_t)(n0 + n) * K + k0 + q * 16;
    *(uint4*)(Thi + off)     = *(const uint4*)(hv);
    *(uint4*)(Thi + off + 8) = *(const uint4*)(hv + 8);
    *(uint4*)(Tlo + off)     = *(const uint4*)(lv);
    *(uint4*)(Tlo + off + 8) = *(const uint4*)(lv + 8);
}

// =====================================================================
// rmsnorm -> hi/lo bf16 row-major
// =====================================================================
__global__ __launch_bounds__(256) void rmsnorm_split(
    const float* __restrict__ x, const float* __restrict__ w,
    __nv_bfloat16* __restrict__ Ohi, __nv_bfloat16* __restrict__ Olo)
{
    __shared__ float red[256];
    const int tid = threadIdx.x;
    const int m = blockIdx.x;
    const float* xp = x + (size_t)m * DIM + tid * 8;
    float4 a = *(const float4*)xp;
    float4 b = *(const float4*)(xp + 4);
    float s = a.x*a.x + a.y*a.y + a.z*a.z + a.w*a.w
            + b.x*b.x + b.y*b.y + b.z*b.z + b.w*b.w;
    red[tid] = s;
    __syncthreads();
    #pragma unroll
    for (int off = 128; off > 0; off >>= 1) {
        if (tid < off) red[tid] += red[tid + off];
        __syncthreads();
    }
    float scale = rsqrtf(red[0] * (1.0f / DIM) + 1e-6f);
    const float* wp = w + tid * 8;
    float4 wa = *(const float4*)wp;
    float4 wb = *(const float4*)(wp + 4);
    float y[8];
    y[0] = a.x*scale*wa.x; y[1] = a.y*scale*wa.y; y[2] = a.z*scale*wa.z; y[3] = a.w*scale*wa.w;
    y[4] = b.x*scale*wb.x; y[5] = b.y*scale*wb.y; y[6] = b.z*scale*wb.z; y[7] = b.w*scale*wb.w;
    __align__(16) __nv_bfloat16 hv[8], lv[8];
    #pragma unroll
    for (int j = 0; j < 8; j++) {
        __nv_bfloat16 h16 = __float2bfloat16(y[j]);
        hv[j] = h16;
        lv[j] = __float2bfloat16(y[j] - __bfloat162float(h16));
    }
    *(uint4*)(Ohi + (size_t)m * DIM + tid * 8) = *(const uint4*)hv;
    *(uint4*)(Olo + (size_t)m * DIM + tid * 8) = *(const uint4*)lv;
}

// =====================================================================
// GEMM core macros shared by gemm_mma / gemm_qkv.
// CTA tile 128(M) x 256(N), warp tile 64x64, 8 warps, 4-stage cp.async.
// =====================================================================
#define GM_STAGES 4
#define GM_STAGE_BYTES 49152
#define GM_SMEM (GM_STAGES * GM_STAGE_BYTES)   // 196608
#define OFF_AH 0
#define OFF_AL 8192
#define OFF_BH 16384
#define OFF_BL 32768

__device__ __forceinline__ uint32_t swz(int r, int g) {
    return (uint32_t)(r * 64 + ((g ^ ((r >> 1) & 3)) << 4));
}

// mainloop shared body: computes acc[4][8][4] for this CTA
template<typename IssueF>
__device__ __forceinline__ void gemm_mainloop(
    float (&acc)[4][8][4], uint32_t sb, int nk, int wm, int wn, int lane,
    IssueF issue_stage)
{
    issue_stage(0, 0); CP_COMMIT();
    issue_stage(1, 1); CP_COMMIT();
    issue_stage(2, 2); CP_COMMIT();

    for (int kc = 0; kc < nk; kc++) {
        CP_WAIT2();
        __syncthreads();
        if (kc + 3 < nk) issue_stage(kc + 3, (kc + 3) & 3);
        CP_COMMIT();

        const uint32_t st = sb + (kc & 3) * GM_STAGE_BYTES;
        #pragma unroll
        for (int h = 0; h < 2; h++) {
            uint32_t ah[4][4], al[4][4];
            #pragma unroll
            for (int mi = 0; mi < 4; mi++) {
                const int r = wm * 64 + mi * 16 + (lane & 15);
                const uint32_t sw = swz(r, h * 2 + (lane >> 4));
                ldsm4(ah[mi], st + OFF_AH + sw);
                ldsm4(al[mi], st + OFF_AL + sw);
            }
            #pragma unroll
            for (int ng = 0; ng < 4; ng++) {
                uint32_t bh[4], bl[4];
                const int r = wn * 64 + ng * 16 + (lane & 15);
                const uint32_t sw = swz(r, h * 2 + (lane >> 4));
                ldsm4(bh, st + OFF_BH + sw);
                ldsm4(bl, st + OFF_BL + sw);
                #pragma unroll
                for (int mi = 0; mi < 4; mi++) {
                    mma_bf16(acc[mi][ng * 2 + 0], ah[mi], bh[0], bh[2]);
                    mma_bf16(acc[mi][ng * 2 + 1], ah[mi], bh[1], bh[3]);
                    mma_bf16(acc[mi][ng * 2 + 0], ah[mi], bl[0], bl[2]);
                    mma_bf16(acc[mi][ng * 2 + 1], ah[mi], bl[1], bl[3]);
                    mma_bf16(acc[mi][ng * 2 + 0], al[mi], bh[0], bh[2]);
                    mma_bf16(acc[mi][ng * 2 + 1], al[mi], bh[1], bh[3]);
                }
            }
        }
        __syncthreads();
    }
}

// =====================================================================
// Generic GEMM: MODE 0: C=A@B+bias; 1: +extra; 2: silu(extra)*(..)->bf16
// =====================================================================
template<int MODE>
__global__ void __launch_bounds__(256, 1) gemm_mma(
    const __nv_bfloat16* __restrict__ Ahi, const __nv_bfloat16* __restrict__ Alo,
    const __nv_bfloat16* __restrict__ Bhi, const __nv_bfloat16* __restrict__ Blo,
    const float* __restrict__ bias, const float* __restrict__ extra,
    float* __restrict__ C, __nv_bfloat16* __restrict__ Chi, __nv_bfloat16* __restrict__ Clo,
    int M, int N, int K)
{
    extern __shared__ char smraw[];
    const uint32_t sb = smem_u32(smraw);
    const int tid = threadIdx.x;
    const int wid = tid >> 5;
    const int lane = tid & 31;
    const int wm = wid & 1;
    const int wn = wid >> 1;
    const int m0 = blockIdx.y * 128;
    const int n0 = blockIdx.x * 256;
    const int nk = K >> 5;
    const int lr = tid >> 2;
    const int lg = tid & 3;

    float acc[4][8][4];
    #pragma unroll
    for (int a = 0; a < 4; a++)
        #pragma unroll
        for (int b = 0; b < 8; b++)
            #pragma unroll
            for (int c = 0; c < 4; c++) acc[a][b][c] = 0.f;

    auto issue_stage = [&](int kc, int slot) {
        const uint32_t st = sb + slot * GM_STAGE_BYTES;
        const int kelem = kc * 32 + lg * 8;
        #pragma unroll
        for (int i = 0; i < 2; i++) {
            const int r = lr + i * 64;
            const uint32_t sw = swz(r, lg);
            cp_async16(st + OFF_AH + sw, Ahi + (size_t)(m0 + r) * K + kelem);
            cp_async16(st + OFF_AL + sw, Alo + (size_t)(m0 + r) * K + kelem);
        }
        #pragma unroll
        for (int i = 0; i < 4; i++) {
            const int r = lr + i * 64;
            const uint32_t sw = swz(r, lg);
            cp_async16(st + OFF_BH + sw, Bhi + (size_t)(n0 + r) * K + kelem);
            cp_async16(st + OFF_BL + sw, Blo + (size_t)(n0 + r) * K + kelem);
        }
    };

    gemm_mainloop(acc, sb, nk, wm, wn, lane, issue_stage);

    const int mb = m0 + wm * 64;
    const int nb = n0 + wn * 64;
    #pragma unroll
    for (int mi = 0; mi < 4; mi++) {
        #pragma unroll
        for (int j = 0; j < 8; j++) {
            const int row = mb + mi * 16 + (lane >> 2);
            const int col = nb + j * 8 + (lane & 3) * 2;
            const float b0 = bias[col], b1 = bias[col + 1];
            #pragma unroll
            for (int half = 0; half < 2; half++) {
                const int rr = row + half * 8;
                float v0 = acc[mi][j][half * 2 + 0] + b0;
                float v1 = acc[mi][j][half * 2 + 1] + b1;
                if (MODE == 1) {
                    const float* ep = extra + (size_t)rr * N + col;
                    v0 += ep[0]; v1 += ep[1];
                }
                if (MODE == 2) {
                    const float* ep = extra + (size_t)rr * N + col;
                    float g0 = ep[0], g1 = ep[1];
                    v0 *= g0 / (1.f + __expf(-g0));
                    v1 *= g1 / (1.f + __expf(-g1));
                    split_store2(Chi, Clo, (size_t)rr * N + col, v0, v1);
                } else {
                    *(float2*)(C + (size_t)rr * N + col) = make_float2(v0, v1);
                }
            }
        }
    }
}

// =====================================================================
// Fused QKV GEMM: B = concat[wq|wk|wv] (N=6144). Epilogue applies RoPE
// + relayout. Each CTA n-range (256 cols) lies in exactly one section.
//   sec 0 (Q): rope * QK_SCALE -> q16h/l (b,h,s,d)
//   sec 1 (K): rope -> out_k fp32 + k16h/l  (b,h,1024+s,d)
//   sec 2 (V): -> out_v fp32 + v16
// =====================================================================
__global__ void __launch_bounds__(256, 1) gemm_qkv(
    const __nv_bfloat16* __restrict__ Ahi, const __nv_bfloat16* __restrict__ Alo,
    const __nv_bfloat16* __restrict__ Bhi, const __nv_bfloat16* __restrict__ Blo,
    const float* __restrict__ bq, const float* __restrict__ bk, const float* __restrict__ bv,
    const float* __restrict__ cosb, const float* __restrict__ sinb,
    float* __restrict__ out_k, float* __restrict__ out_v,
    __nv_bfloat16* __restrict__ Qh, __nv_bfloat16* __restrict__ Ql,
    __nv_bfloat16* __restrict__ Kh, __nv_bfloat16* __restrict__ Kl,
    __nv_bfloat16* __restrict__ V16)
{
    extern __shared__ char smraw[];
    const uint32_t sb = smem_u32(smraw);
    const int tid = threadIdx.x;
    const int wid = tid >> 5;
    const int lane = tid & 31;
    const int wm = wid & 1;
    const int wn = wid >> 1;
    const int m0 = blockIdx.y * 128;
    const int n0 = blockIdx.x * 256;
    const int K = DIM;
    const int nk = K >> 5;
    const int lr = tid >> 2;
    const int lg = tid & 3;
    const int sec = n0 >> 11;
    const float* bias = (sec == 0) ? bq : ((sec == 1) ? bk : bv);

    float acc[4][8][4];
    #pragma unroll
    for (int a = 0; a < 4; a++)
        #pragma unroll
        for (int b = 0; b < 8; b++)
            #pragma unroll
            for (int c = 0; c < 4; c++) acc[a][b][c] = 0.f;

    auto issue_stage = [&](int kc, int slot) {
        const uint32_t st = sb + slot * GM_STAGE_BYTES;
        const int kelem = kc * 32 + lg * 8;
        #pragma unroll
        for (int i = 0; i < 2; i++) {
            const int r = lr + i * 64;
            const uint32_t sw = swz(r, lg);
            cp_async16(st + OFF_AH + sw, Ahi + (size_t)(m0 + r) * K + kelem);
            cp_async16(st + OFF_AL + sw, Alo + (size_t)(m0 + r) * K + kelem);
        }
        #pragma unroll
        for (int i = 0; i < 4; i++) {
            const int r = lr + i * 64;
            const uint32_t sw = swz(r, lg);
            cp_async16(st + OFF_BH + sw, Bhi + (size_t)(n0 + r) * K + kelem);
            cp_async16(st + OFF_BL + sw, Blo + (size_t)(n0 + r) * K + kelem);
        }
    };

    gemm_mainloop(acc, sb, nk, wm, wn, lane, issue_stage);

    const int mb = m0 + wm * 64;
    const int nb = n0 + wn * 64;
    #pragma unroll
    for (int mi = 0; mi < 4; mi++) {
        #pragma unroll
        for (int j = 0; j < 8; j++) {
            const int row = mb + mi * 16 + (lane >> 2);
            const int col = nb + j * 8 + (lane & 3) * 2;
            const float b0 = bias[col & 2047], b1 = bias[(col & 2047) + 1];
            const int nc = col & 2047;
            const int h = nc >> 7;
            const int d = nc & 127;
            #pragma unroll
            for (int half = 0; half < 2; half++) {
                const int rr = row + half * 8;
                float v0 = acc[mi][j][half * 2 + 0] + b0;
                float v1 = acc[mi][j][half * 2 + 1] + b1;
                const int bi = rr >> 11;
                const int s = rr & 2047;
                if (sec < 2) {
                    const int i2 = d >> 1;
                    const float c = cosb[(PREV_LEN + s) * 64 + i2];
                    const float sn = sinb[(PREV_LEN + s) * 64 + i2];
                    const float r0 = v0 * c - v1 * sn;
                    const float r1 = v0 * sn + v1 * c;
                    if (sec == 0) {
                        split_store2(Qh, Ql,
                            ((size_t)(bi * HEADS + h) * S_LEN + s) * HD + d,
                            r0 * QK_SCALE, r1 * QK_SCALE);
                    } else {
                        const size_t off = ((size_t)(bi * HEADS + h) * T_LEN + PREV_LEN + s) * HD + d;
                        *(float2*)(out_k + off) = make_float2(r0, r1);
                        split_store2(Kh, Kl, off, r0, r1);
                    }
                } else {
                    const size_t off = ((size_t)(bi * HEADS + h) * T_LEN + PREV_LEN + s) * HD + d;
                    *(float2*)(out_v + off) = make_float2(v0, v1);
                    __nv_bfloat162 bb = __floats2bfloat162_rn(v0, v1);
                    *(__nv_bfloat162*)(V16 + off) = bb;
                }
            }
        }
    }
}

// ---------------- cache copies ----------------
__global__ __launch_bounds__(256) void copy_cache_k(
    const float* __restrict__ in, float* __restrict__ out,
    __nv_bfloat16* __restrict__ Kh, __nv_bfloat16* __restrict__ Kl)
{
    int idx = blockIdx.x * 256 + threadIdx.x;   // 2^20 f4
    int bh  = idx >> 15;
    int rem = idx & 32767;
    float4 v = ((const float4*)in)[idx];
    size_t off4 = (size_t)bh * (T_LEN * HD / 4) + rem;
    ((float4*)out)[off4] = v;
    size_t off = off4 * 4;
    split_store2(Kh, Kl, off,     v.x, v.y);
    split_store2(Kh, Kl, off + 2, v.z, v.w);
}

__global__ __launch_bounds__(256) void copy_cache_v(
    const float* __restrict__ in, float* __restrict__ out,
    __nv_bfloat16* __restrict__ V16)
{
    int idx = blockIdx.x * 256 + threadIdx.x;
    int bh  = idx >> 15;
    int rem = idx & 32767;
    float4 v = ((const float4*)in)[idx];
    size_t off4 = (size_t)bh * (T_LEN * HD / 4) + rem;
    ((float4*)out)[off4] = v;
    __align__(8) __nv_bfloat16 bv[4];
    bv[0] = __float2bfloat16(v.x); bv[1] = __float2bfloat16(v.y);
    bv[2] = __float2bfloat16(v.z); bv[3] = __float2bfloat16(v.w);
    *(uint2*)(V16 + off4 * 4) = *(const uint2*)bv;
}

// =====================================================================
// HMMA flash attention (proven; mtile order reversed for load balance).
// =====================================================================
#define FBM 128
#define FBN 64
#define F_OFF_QH 0
#define F_OFF_QL 32768
#define F_OFF_ST 65536
#define F_STAGE  49152
#define F_SMEM   (F_OFF_ST + 2 * F_STAGE)   // 163840

__device__ __forceinline__ uint32_t swz256(int r, int g) {
    return (uint32_t)((r << 8) + (((g ^ (r & 7)) & 15) << 4));
}

__global__ void __launch_bounds__(256) flash_mma(
    const __nv_bfloat16* __restrict__ Qh, const __nv_bfloat16* __restrict__ Ql,
    const __nv_bfloat16* __restrict__ Kh, const __nv_bfloat16* __restrict__ Kl,
    const __nv_bfloat16* __restrict__ V16,
    __nv_bfloat16* __restrict__ Ohi, __nv_bfloat16* __restrict__ Olo)
{
    extern __shared__ char smraw[];
    const uint32_t sb = smem_u32(smraw);
    const int tid = threadIdx.x;
    const int wid = tid >> 5;
    const int lane = tid & 31;
    const int mtile = gridDim.x - 1 - blockIdx.x;   // long-KV tiles first
    const int bh = blockIdx.y;
    const int m0 = mtile * FBM;
    const int jend = (PREV_LEN + m0 + FBM) / FBN;
    const int mask_start = (PREV_LEN + m0) / FBN;

    {
        const size_t qo = ((size_t)bh * S_LEN + m0) * HD;
        for (int i = tid; i < 2048; i += 256) {
            int r = i >> 4, g = i & 15;
            uint32_t sw = swz256(r, g);
            cp_async16(sb + F_OFF_QH + sw, Qh + qo + (size_t)r * HD + g * 8);
            cp_async16(sb + F_OFF_QL + sw, Ql + qo + (size_t)r * HD + g * 8);
        }
        CP_COMMIT();
    }

    auto issue_kv = [&](int jt, int slot) {
        const uint32_t st = sb + F_OFF_ST + slot * F_STAGE;
        const size_t ko = ((size_t)bh * T_LEN + jt * FBN) * HD;
        for (int i = tid; i < 1024; i += 256) {
            int r = i >> 4, g = i & 15;
            uint32_t sw = swz256(r, g);
            size_t go = ko + (size_t)r * HD + g * 8;
            cp_async16(st + sw, Kh + go);
            cp_async16(st + 16384 + sw, Kl + go);
            cp_async16(st + 32768 + sw, V16 + go);
        }
    };
    issue_kv(0, 0); CP_COMMIT();
    issue_kv(1, 1); CP_COMMIT();

    float of[16][4];
    #pragma unroll
    for (int i = 0; i < 16; i++)
        #pragma unroll
        for (int j = 0; j < 4; j++) of[i][j] = 0.f;
    float mrow0 = -1e30f, mrow1 = -1e30f, lrow0 = 0.f, lrow1 = 0.f;

    const int arow = wid * 16 + (lane & 15);
    const int agr  = lane >> 4;

    for (int jt = 0; jt < jend; jt++) {
        CP_WAIT1();
        __syncthreads();
        const uint32_t st = sb + F_OFF_ST + (jt & 1) * F_STAGE;
        const int t0 = jt * FBN;

        float sf[8][4];
        #pragma unroll
        for (int i = 0; i < 8; i++)
            #pragma unroll
            for (int j = 0; j < 4; j++) sf[i][j] = 0.f;

        #pragma unroll
        for (int pass = 0; pass < 3; pass++) {
            const uint32_t qb = sb + (pass == 2 ? F_OFF_QL : F_OFF_QH);
            const uint32_t kb = st + (pass == 1 ? 16384 : 0);
            #pragma unroll
            for (int kt = 0; kt < 8; kt++) {
                uint32_t a[4];
                ldsm4(a, qb + swz256(arow, kt * 2 + agr));
                #pragma unroll
                for (int nb = 0; nb < 4; nb++) {
                    uint32_t b[4];
                    ldsm4(b, kb + swz256(nb * 16 + (lane & 15), kt * 2 + agr));
                    mma_bf16(sf[nb * 2 + 0], a, b[0], b[2]);
                    mma_bf16(sf[nb * 2 + 1], a, b[1], b[3]);
                }
            }
        }

        if (jt >= mask_start) {
            const int rb = m0 + wid * 16 + (lane >> 2);
            const int cb = t0 + (lane & 3) * 2;
            #pragma unroll
            for (int nt = 0; nt < 8; nt++) {
                const int c0 = cb + nt * 8;
                if (c0     > PREV_LEN + rb)     sf[nt][0] = -1e30f;
                if (c0 + 1 > PREV_LEN + rb)     sf[nt][1] = -1e30f;
                if (c0     > PREV_LEN + rb + 8) sf[nt][2] = -1e30f;
                if (c0 + 1 > PREV_LEN + rb + 8) sf[nt][3] = -1e30f;
            }
        }

        float mx0 = -1e30f, mx1 = -1e30f;
        #pragma unroll
        for (int nt = 0; nt < 8; nt++) {
            mx0 = fmaxf(mx0, fmaxf(sf[nt][0], sf[nt][1]));
            mx1 = fmaxf(mx1, fmaxf(sf[nt][2], sf[nt][3]));
        }
        mx0 = fmaxf(mx0, __shfl_xor_sync(0xFFFFFFFF, mx0, 1));
        mx0 = fmaxf(mx0, __shfl_xor_sync(0xFFFFFFFF, mx0, 2));
        mx1 = fmaxf(mx1, __shfl_xor_sync(0xFFFFFFFF, mx1, 1));
        mx1 = fmaxf(mx1, __shfl_xor_sync(0xFFFFFFFF, mx1, 2));
        const float nm0 = fmaxf(mrow0, mx0);
        const float nm1 = fmaxf(mrow1, mx1);
        const float al0 = __expf(mrow0 - nm0);
        const float al1 = __expf(mrow1 - nm1);
        mrow0 = nm0; mrow1 = nm1;

        float rs0 = 0.f, rs1 = 0.f;
        #pragma unroll
        for (int nt = 0; nt < 8; nt++) {
            sf[nt][0] = __expf(sf[nt][0] - nm0);
            sf[nt][1] = __expf(sf[nt][1] - nm0);
            sf[nt][2] = __expf(sf[nt][2] - nm1);
            sf[nt][3] = __expf(sf[nt][3] - nm1);
            rs0 += sf[nt][0] + sf[nt][1];
            rs1 += sf[nt][2] + sf[nt][3];
        }
        rs0 += __shfl_xor_sync(0xFFFFFFFF, rs0, 1);
        rs0 += __shfl_xor_sync(0xFFFFFFFF, rs0, 2);
        rs1 += __shfl_xor_sync(0xFFFFFFFF, rs1, 1);
        rs1 += __shfl_xor_sync(0xFFFFFFFF, rs1, 2);
        lrow0 = lrow0 * al0 + rs0;
        lrow1 = lrow1 * al1 + rs1;

        #pragma unroll
        for (int nt = 0; nt < 16; nt++) {
            of[nt][0] *= al0; of[nt][1] *= al0;
            of[nt][2] *= al1; of[nt][3] *= al1;
        }

        #pragma unroll
        for (int kt = 0; kt < 4; kt++) {
            uint32_t a[4];
            a[0] = pack_bf16(sf[2 * kt][0],     sf[2 * kt][1]);
            a[1] = pack_bf16(sf[2 * kt][2],     sf[2 * kt][3]);
            a[2] = pack_bf16(sf[2 * kt + 1][0], sf[2 * kt + 1][1]);
            a[3] = pack_bf16(sf[2 * kt + 1][2], sf[2 * kt + 1][3]);
            const int vrow = kt * 16 + ((lane >> 3) & 1) * 8 + (lane & 7);
            #pragma unroll
            for (int nb = 0; nb < 8; nb++) {
                uint32_t b[4];
                ldsm4t(b, st + 32768 + swz256(vrow, nb * 2 + ((lane >> 4) & 1)));
                mma_bf16(of[nb * 2 + 0], a, b[0], b[1]);
                mma_bf16(of[nb * 2 + 1], a, b[2], b[3]);
            }
        }

        __syncthreads();
        if (jt + 2 < jend) issue_kv(jt + 2, jt & 1);
        CP_COMMIT();
    }

    const float inv0 = 1.f / lrow0;
    const float inv1 = 1.f / lrow1;
    const int b = bh >> 4, h = bh & 15;
    const int r0 = m0 + wid * 16 + (lane >> 2);
    #pragma unroll
    for (int nt = 0; nt < 16; nt++) {
        const int gc = h * HD + nt * 8 + (lane & 3) * 2;
        split_store2(Ohi, Olo, (size_t)(b * S_LEN + r0) * DIM + gc,
                     of[nt][0] * inv0, of[nt][1] * inv0);
        split_store2(Ohi, Olo, (size_t)(b * S_LEN + r0 + 8) * DIM + gc,
                     of[nt][2] * inv1, of[nt][3] * inv1);
    }
}

// ---------------- launch ----------------
extern "C" void kernel_launch(void* const* d_in, const int* in_sizes, int n_in,
                              void* d_out, int out_size)
{
    const float* x          = (const float*)d_in[0];
    const float* k_cache    = (const float*)d_in[1];
    const float* v_cache    = (const float*)d_in[2];
    const float* attn_norm_w= (const float*)d_in[3];
    const float* ffn_norm_w = (const float*)d_in[4];
    const float* wq = (const float*)d_in[5];
    const float* bq = (const float*)d_in[6];
    const float* wk = (const float*)d_in[7];
    const float* bk = (const float*)d_in[8];
    const float* wv = (const float*)d_in[9];
    const float* bv = (const float*)d_in[10];
    const float* wo = (const float*)d_in[11];
    const float* bo = (const float*)d_in[12];
    const float* w_gate = (const float*)d_in[13];
    const float* b_gate = (const float*)d_in[14];
    const float* w_val  = (const float*)d_in[15];
    const float* b_val  = (const float*)d_in[16];
    const float* w_proj = (const float*)d_in[17];
    const float* b_proj = (const float*)d_in[18];
    const float* fcos   = (const float*)d_in[19];
    const float* fsin   = (const float*)d_in[20];

    float* out_x = (float*)d_out;
    float* out_k = out_x + OUT_X_ELEMS;
    float* out_v = out_k + OUT_KV_ELEMS;

    float *p_x1, *p_g;
    __nv_bfloat16 *p_hA_hi, *p_hA_lo, *p_h2_hi, *p_h2_lo, *p_o_hi, *p_o_lo, *p_gt_hi, *p_gt_lo;
    __nv_bfloat16 *p_q16h, *p_q16l, *p_k16h, *p_k16l, *p_v16;
    __nv_bfloat16 *p_wqkv_hi, *p_wqkv_lo, *p_wo_hi, *p_wo_lo;
    __nv_bfloat16 *p_wg_hi, *p_wg_lo, *p_wv2_hi, *p_wv2_lo, *p_wp_hi, *p_wp_lo;

    cudaGetSymbolAddress((void**)&p_x1, g_x1);
    cudaGetSymbolAddress((void**)&p_g,  g_g);
    cudaGetSymbolAddress((void**)&p_hA_hi, g_hA_hi);
    cudaGetSymbolAddress((void**)&p_hA_lo, g_hA_lo);
    cudaGetSymbolAddress((void**)&p_h2_hi, g_h2_hi);
    cudaGetSymbolAddress((void**)&p_h2_lo, g_h2_lo);
    cudaGetSymbolAddress((void**)&p_o_hi,  g_o_hi);
    cudaGetSymbolAddress((void**)&p_o_lo,  g_o_lo);
    cudaGetSymbolAddress((void**)&p_gt_hi, g_gt_hi);
    cudaGetSymbolAddress((void**)&p_gt_lo, g_gt_lo);
    cudaGetSymbolAddress((void**)&p_q16h, g_q16h);
    cudaGetSymbolAddress((void**)&p_q16l, g_q16l);
    cudaGetSymbolAddress((void**)&p_k16h, g_k16h);
    cudaGetSymbolAddress((void**)&p_k16l, g_k16l);
    cudaGetSymbolAddress((void**)&p_v16,  g_v16);
    cudaGetSymbolAddress((void**)&p_wqkv_hi, g_wqkv_hi);
    cudaGetSymbolAddress((void**)&p_wqkv_lo, g_wqkv_lo);
    cudaGetSymbolAddress((void**)&p_wo_hi, g_wo_hi);
    cudaGetSymbolAddress((void**)&p_wo_lo, g_wo_lo);
    cudaGetSymbolAddress((void**)&p_wg_hi, g_wg_hi);
    cudaGetSymbolAddress((void**)&p_wg_lo, g_wg_lo);
    cudaGetSymbolAddress((void**)&p_wv2_hi, g_wv2_hi);
    cudaGetSymbolAddress((void**)&p_wv2_lo, g_wv2_lo);
    cudaGetSymbolAddress((void**)&p_wp_hi, g_wp_hi);
    cudaGetSymbolAddress((void**)&p_wp_lo, g_wp_lo);

    cudaFuncSetAttribute(gemm_mma<0>, cudaFuncAttributeMaxDynamicSharedMemorySize, GM_SMEM);
    cudaFuncSetAttribute(gemm_mma<1>, cudaFuncAttributeMaxDynamicSharedMemorySize, GM_SMEM);
    cudaFuncSetAttribute(gemm_mma<2>, cudaFuncAttributeMaxDynamicSharedMemorySize, GM_SMEM);
    cudaFuncSetAttribute(gemm_qkv,   cudaFuncAttributeMaxDynamicSharedMemorySize, GM_SMEM);
    cudaFuncSetAttribute(flash_mma, cudaFuncAttributeMaxDynamicSharedMemorySize, F_SMEM);

    // ---- weight conversion + transpose (grid: K/32, N/128) ----
    weight_conv_t<<<dim3(64, 16), 256>>>(wq, p_wqkv_hi,                p_wqkv_lo,                DIM, DIM);
    weight_conv_t<<<dim3(64, 16), 256>>>(wk, p_wqkv_hi + DIM * DIM,    p_wqkv_lo + DIM * DIM,    DIM, DIM);
    weight_conv_t<<<dim3(64, 16), 256>>>(wv, p_wqkv_hi + 2 * DIM * DIM,p_wqkv_lo + 2 * DIM * DIM,DIM, DIM);
    weight_conv_t<<<dim3(64, 16), 256>>>(wo, p_wo_hi, p_wo_lo, DIM, DIM);
    weight_conv_t<<<dim3(64, 64), 256>>>(w_gate, p_wg_hi,  p_wg_lo,  FF_DIM, DIM);
    weight_conv_t<<<dim3(64, 64), 256>>>(w_val,  p_wv2_hi, p_wv2_lo, FF_DIM, DIM);
    weight_conv_t<<<dim3(256, 16), 256>>>(w_proj, p_wp_hi, p_wp_lo, DIM, FF_DIM);

    // ---- attention block ----
    rmsnorm_split<<<ROWS, 256>>>(x, attn_norm_w, p_hA_hi, p_hA_lo);
    gemm_qkv<<<dim3(24, 32), 256, GM_SMEM>>>(
        p_hA_hi, p_hA_lo, p_wqkv_hi, p_wqkv_lo, bq, bk, bv, fcos, fsin,
        out_k, out_v, p_q16h, p_q16l, p_k16h, p_k16l, p_v16);

    copy_cache_k<<<4096, 256>>>(k_cache, out_k, p_k16h, p_k16l);
    copy_cache_v<<<4096, 256>>>(v_cache, out_v, p_v16);

    flash_mma<<<dim3(S_LEN / FBM, BATCH * HEADS), 256, F_SMEM>>>(
        p_q16h, p_q16l, p_k16h, p_k16l, p_v16, p_o_hi, p_o_lo);

    gemm_mma<1><<<dim3(8, 32), 256, GM_SMEM>>>(
        p_o_hi, p_o_lo, p_wo_hi, p_wo_lo, bo, x, p_x1, nullptr, nullptr, ROWS, DIM, DIM);

    // ---- ffn block ----
    rmsnorm_split<<<ROWS, 256>>>(p_x1, ffn_norm_w, p_h2_hi, p_h2_lo);
    gemm_mma<0><<<dim3(32, 32), 256, GM_SMEM>>>(
        p_h2_hi, p_h2_lo, p_wg_hi, p_wg_lo, b_gate, nullptr, p_g, nullptr, nullptr, ROWS, FF_DIM, DIM);
    gemm_mma<2><<<dim3(32, 32), 256, GM_SMEM>>>(
        p_h2_hi, p_h2_lo, p_wv2_hi, p_wv2_lo, b_val, p_g, nullptr, p_gt_hi, p_gt_lo, ROWS, FF_DIM, DIM);
    gemm_mma<1><<<dim3(8, 32), 256, GM_SMEM>>>(
        p_gt_hi, p_gt_lo, p_wp_hi, p_wp_lo, b_proj, p_x1, out_x, nullptr, nullptr, ROWS, DIM, FF_DIM);
}

// round 7
// speedup vs baseline: 1.3725x; 1.3725x over previous
#include <cuda_runtime.h>
#include <cuda_bf16.h>
#include <cuda_fp16.h>
#include <cstdint>

// ---------------- problem constants ----------------
#define BATCH 2
#define S_LEN 2048
#define PREV_LEN 1024
#define T_LEN 3072
#define DIM 2048
#define HEADS 16
#define HD 128
#define FF_DIM 8192
#define ROWS (BATCH * S_LEN)  // 4096
#define QK_SCALE 0.08838834764831845f

#define OUT_X_ELEMS  (BATCH * S_LEN * DIM)
#define OUT_KV_ELEMS (BATCH * HEADS * T_LEN * HD)

// ================= PTX helpers (portable sm_80+) ====
__device__ __forceinline__ uint32_t smem_u32(const void* p) {
    uint32_t a;
    asm("{ .reg .u64 t; cvta.to.shared.u64 t, %1; cvt.u32.u64 %0, t; }" : "=r"(a) : "l"(p));
    return a;
}
__device__ __forceinline__ void cp_async16(uint32_t smem, const void* g) {
    asm volatile("cp.async.cg.shared.global [%0], [%1], 16;" :: "r"(smem), "l"(g) : "memory");
}
#define CP_COMMIT() asm volatile("cp.async.commit_group;" ::: "memory")
#define CP_WAIT2()  asm volatile("cp.async.wait_group 2;" ::: "memory")
#define CP_WAIT1()  asm volatile("cp.async.wait_group 1;" ::: "memory")

__device__ __forceinline__ void ldsm4(uint32_t* r, uint32_t addr) {
    asm volatile("ldmatrix.sync.aligned.m8n8.x4.shared.b16 {%0,%1,%2,%3}, [%4];"
        : "=r"(r[0]), "=r"(r[1]), "=r"(r[2]), "=r"(r[3]) : "r"(addr));
}
__device__ __forceinline__ void ldsm4t(uint32_t* r, uint32_t addr) {
    asm volatile("ldmatrix.sync.aligned.m8n8.x4.trans.shared.b16 {%0,%1,%2,%3}, [%4];"
        : "=r"(r[0]), "=r"(r[1]), "=r"(r[2]), "=r"(r[3]) : "r"(addr));
}
__device__ __forceinline__ void mma_bf16(float* c, const uint32_t* a, uint32_t b0, uint32_t b1) {
    asm volatile(
        "mma.sync.aligned.m16n8k16.row.col.f32.bf16.bf16.f32 "
        "{%0,%1,%2,%3}, {%4,%5,%6,%7}, {%8,%9}, {%0,%1,%2,%3};"
        : "+f"(c[0]), "+f"(c[1]), "+f"(c[2]), "+f"(c[3])
        : "r"(a[0]), "r"(a[1]), "r"(a[2]), "r"(a[3]), "r"(b0), "r"(b1));
}
__device__ __forceinline__ void mma_f16(float* c, const uint32_t* a, uint32_t b0, uint32_t b1) {
    asm volatile(
        "mma.sync.aligned.m16n8k16.row.col.f32.f16.f16.f32 "
        "{%0,%1,%2,%3}, {%4,%5,%6,%7}, {%8,%9}, {%0,%1,%2,%3};"
        : "+f"(c[0]), "+f"(c[1]), "+f"(c[2]), "+f"(c[3])
        : "r"(a[0]), "r"(a[1]), "r"(a[2]), "r"(a[3]), "r"(b0), "r"(b1));
}
__device__ __forceinline__ uint32_t pack_bf16(float a, float b) {
    __nv_bfloat162 t = __floats2bfloat162_rn(a, b);
    return *(uint32_t*)&t;
}
__device__ __forceinline__ void split_store2(
    __nv_bfloat16* Hi, __nv_bfloat16* Lo, size_t off, float a, float b)
{
    __nv_bfloat16 ha = __float2bfloat16(a), hb = __float2bfloat16(b);
    __nv_bfloat162 hh; hh.x = ha; hh.y = hb;
    __nv_bfloat162 ll;
    ll.x = __float2bfloat16(a - __bfloat162float(ha));
    ll.y = __float2bfloat16(b - __bfloat162float(hb));
    *(__nv_bfloat162*)(Hi + off) = hh;
    *(__nv_bfloat162*)(Lo + off) = ll;
}

// ---------------- scratch (device globals) --------
__device__ float g_x1 [ROWS * DIM];
__device__ float g_g  [ROWS * FF_DIM];
// fp16 single activations (GEMM A operands)
__device__ __half g_hA16 [ROWS * DIM];
__device__ __half g_h216 [ROWS * DIM];
__device__ __half g_o16  [ROWS * DIM];
__device__ __half g_gt16 [ROWS * FF_DIM];
// bf16 attention operands (b,h,s/t,d) — flash kernel unchanged
__device__ __nv_bfloat16 g_q16h [ROWS * DIM];
__device__ __nv_bfloat16 g_q16l [ROWS * DIM];
__device__ __nv_bfloat16 g_k16h [OUT_KV_ELEMS];
__device__ __nv_bfloat16 g_k16l [OUT_KV_ELEMS];
__device__ __nv_bfloat16 g_v16  [OUT_KV_ELEMS];
// fp16 hi/lo transposed weights [N][K]
__device__ __half g_wqkv_hi[3 * DIM * DIM];
__device__ __half g_wqkv_lo[3 * DIM * DIM];
__device__ __half g_wo_hi [DIM * DIM];
__device__ __half g_wo_lo [DIM * DIM];
__device__ __half g_wg_hi [DIM * FF_DIM];
__device__ __half g_wg_lo [DIM * FF_DIM];
__device__ __half g_wv2_hi[DIM * FF_DIM];
__device__ __half g_wv2_lo[DIM * FF_DIM];
__device__ __half g_wp_hi [FF_DIM * DIM];
__device__ __half g_wp_lo [FF_DIM * DIM];

// =====================================================================
// Weight converter + transpose: W[K][N] fp32 -> Wt[N][K] fp16 hi/lo.
// grid (K/32, N/128), 256 threads.
// =====================================================================
__global__ __launch_bounds__(256) void weight_conv_t(
    const float* __restrict__ W, __half* __restrict__ Thi,
    __half* __restrict__ Tlo, int N, int K)
{
    __shared__ float tile[32][133];
    const int k0 = blockIdx.x * 32, n0 = blockIdx.y * 128;
    const int tid = threadIdx.x;
    {
        const int kr = tid >> 3;
        const int nq = (tid & 7) * 16;
        const float* src = W + (size_t)(k0 + kr) * N + n0 + nq;
        #pragma unroll
        for (int u = 0; u < 4; u++) {
            float4 v = *(const float4*)(src + u * 4);
            tile[kr][nq + u * 4 + 0] = v.x;
            tile[kr][nq + u * 4 + 1] = v.y;
            tile[kr][nq + u * 4 + 2] = v.z;
            tile[kr][nq + u * 4 + 3] = v.w;
        }
    }
    __syncthreads();
    const int n = tid >> 1;
    const int q = tid & 1;
    __align__(16) __half hv[16], lv[16];
    #pragma unroll
    for (int u = 0; u < 16; u++) {
        float v = tile[q * 16 + u][n];
        __half h = __float2half(v);
        hv[u] = h;
        lv[u] = __float2half(v - __half2float(h));
    }
    const size_t off = (size_t)(n0 + n) * K + k0 + q * 16;
    *(uint4*)(Thi + off)     = *(const uint4*)(hv);
    *(uint4*)(Thi + off + 8) = *(const uint4*)(hv + 8);
    *(uint4*)(Tlo + off)     = *(const uint4*)(lv);
    *(uint4*)(Tlo + off + 8) = *(const uint4*)(lv + 8);
}

// =====================================================================
// rmsnorm -> single fp16 row-major
// =====================================================================
__global__ __launch_bounds__(256) void rmsnorm_h(
    const float* __restrict__ x, const float* __restrict__ w,
    __half* __restrict__ O16)
{
    __shared__ float red[256];
    const int tid = threadIdx.x;
    const int m = blockIdx.x;
    const float* xp = x + (size_t)m * DIM + tid * 8;
    float4 a = *(const float4*)xp;
    float4 b = *(const float4*)(xp + 4);
    float s = a.x*a.x + a.y*a.y + a.z*a.z + a.w*a.w
            + b.x*b.x + b.y*b.y + b.z*b.z + b.w*b.w;
    red[tid] = s;
    __syncthreads();
    #pragma unroll
    for (int off = 128; off > 0; off >>= 1) {
        if (tid < off) red[tid] += red[tid + off];
        __syncthreads();
    }
    float scale = rsqrtf(red[0] * (1.0f / DIM) + 1e-6f);
    const float* wp = w + tid * 8;
    float4 wa = *(const float4*)wp;
    float4 wb = *(const float4*)(wp + 4);
    float y[8];
    y[0] = a.x*scale*wa.x; y[1] = a.y*scale*wa.y; y[2] = a.z*scale*wa.z; y[3] = a.w*scale*wa.w;
    y[4] = b.x*scale*wb.x; y[5] = b.y*scale*wb.y; y[6] = b.z*scale*wb.z; y[7] = b.w*scale*wb.w;
    __align__(16) __half hv[8];
    #pragma unroll
    for (int j = 0; j < 8; j++) hv[j] = __float2half(y[j]);
    *(uint4*)(O16 + (size_t)m * DIM + tid * 8) = *(const uint4*)hv;
}

// =====================================================================
// fp16 one-sided-split GEMM core. CTA 128x256, warp 64x64, 8 warps,
// K-chunk 32, 4-stage cp.async. A single fp16 [M][K]; B fp16 hi/lo [N][K].
// C = A@Bh + A@Bl  (2 MMA passes).
// =====================================================================
#define GM_STAGES 4
#define GM_STAGE_BYTES 40960
#define GM_SMEM (GM_STAGES * GM_STAGE_BYTES)   // 163840
#define OFF_A  0
#define OFF_BH 8192
#define OFF_BL 24576

__device__ __forceinline__ uint32_t swz(int r, int g) {
    return (uint32_t)(r * 64 + ((g ^ ((r >> 1) & 3)) << 4));
}

template<typename IssueF>
__device__ __forceinline__ void gemm_mainloop(
    float (&acc)[4][8][4], uint32_t sb, int nk, int wm, int wn, int lane,
    IssueF issue_stage)
{
    issue_stage(0, 0); CP_COMMIT();
    issue_stage(1, 1); CP_COMMIT();
    issue_stage(2, 2); CP_COMMIT();

    for (int kc = 0; kc < nk; kc++) {
        CP_WAIT2();
        __syncthreads();
        if (kc + 3 < nk) issue_stage(kc + 3, (kc + 3) & 3);
        CP_COMMIT();

        const uint32_t st = sb + (kc & 3) * GM_STAGE_BYTES;
        #pragma unroll
        for (int h = 0; h < 2; h++) {
            uint32_t a[4][4];
            #pragma unroll
            for (int mi = 0; mi < 4; mi++) {
                const int r = wm * 64 + mi * 16 + (lane & 15);
                ldsm4(a[mi], st + OFF_A + swz(r, h * 2 + (lane >> 4)));
            }
            #pragma unroll
            for (int ng = 0; ng < 4; ng++) {
                uint32_t bh[4], bl[4];
                const int r = wn * 64 + ng * 16 + (lane & 15);
                const uint32_t sw = swz(r, h * 2 + (lane >> 4));
                ldsm4(bh, st + OFF_BH + sw);
                ldsm4(bl, st + OFF_BL + sw);
                #pragma unroll
                for (int mi = 0; mi < 4; mi++) {
                    mma_f16(acc[mi][ng * 2 + 0], a[mi], bh[0], bh[2]);
                    mma_f16(acc[mi][ng * 2 + 1], a[mi], bh[1], bh[3]);
                    mma_f16(acc[mi][ng * 2 + 0], a[mi], bl[0], bl[2]);
                    mma_f16(acc[mi][ng * 2 + 1], a[mi], bl[1], bl[3]);
                }
            }
        }
        __syncthreads();
    }
}

#define GEMM_ISSUE_LAMBDA(A16, Bhi, Blo, m0, n0, K)                             \
    auto issue_stage = [&](int kc, int slot) {                                  \
        const uint32_t st = sb + slot * GM_STAGE_BYTES;                         \
        const int kelem = kc * 32 + lg * 8;                                     \
        _Pragma("unroll")                                                       \
        for (int i = 0; i < 2; i++) {                                           \
            const int r = lr + i * 64;                                          \
            cp_async16(st + OFF_A + swz(r, lg), A16 + (size_t)(m0 + r) * K + kelem); \
        }                                                                       \
        _Pragma("unroll")                                                       \
        for (int i = 0; i < 4; i++) {                                           \
            const int r = lr + i * 64;                                          \
            const uint32_t sw = swz(r, lg);                                     \
            cp_async16(st + OFF_BH + sw, Bhi + (size_t)(n0 + r) * K + kelem);   \
            cp_async16(st + OFF_BL + sw, Blo + (size_t)(n0 + r) * K + kelem);   \
        }                                                                       \
    };

// =====================================================================
// Generic GEMM: MODE 0: C=A@B+bias; 1: +extra (fp32 out);
//               2: silu(extra)*(A@B+bias) -> fp16 out C16
// =====================================================================
template<int MODE>
__global__ void __launch_bounds__(256, 1) gemm_mma(
    const __half* __restrict__ A16,
    const __half* __restrict__ Bhi, const __half* __restrict__ Blo,
    const float* __restrict__ bias, const float* __restrict__ extra,
    float* __restrict__ C, __half* __restrict__ C16,
    int M, int N, int K)
{
    extern __shared__ char smraw[];
    const uint32_t sb = smem_u32(smraw);
    const int tid = threadIdx.x;
    const int wid = tid >> 5;
    const int lane = tid & 31;
    const int wm = wid & 1;
    const int wn = wid >> 1;
    const int m0 = blockIdx.y * 128;
    const int n0 = blockIdx.x * 256;
    const int nk = K >> 5;
    const int lr = tid >> 2;
    const int lg = tid & 3;

    float acc[4][8][4];
    #pragma unroll
    for (int a = 0; a < 4; a++)
        #pragma unroll
        for (int b = 0; b < 8; b++)
            #pragma unroll
            for (int c = 0; c < 4; c++) acc[a][b][c] = 0.f;

    GEMM_ISSUE_LAMBDA(A16, Bhi, Blo, m0, n0, K)
    gemm_mainloop(acc, sb, nk, wm, wn, lane, issue_stage);

    const int mb = m0 + wm * 64;
    const int nb = n0 + wn * 64;
    #pragma unroll
    for (int mi = 0; mi < 4; mi++) {
        #pragma unroll
        for (int j = 0; j < 8; j++) {
            const int row = mb + mi * 16 + (lane >> 2);
            const int col = nb + j * 8 + (lane & 3) * 2;
            const float b0 = bias[col], b1 = bias[col + 1];
            #pragma unroll
            for (int half = 0; half < 2; half++) {
                const int rr = row + half * 8;
                float v0 = acc[mi][j][half * 2 + 0] + b0;
                float v1 = acc[mi][j][half * 2 + 1] + b1;
                if (MODE == 1) {
                    const float* ep = extra + (size_t)rr * N + col;
                    v0 += ep[0]; v1 += ep[1];
                }
                if (MODE == 2) {
                    const float* ep = extra + (size_t)rr * N + col;
                    float g0 = ep[0], g1 = ep[1];
                    v0 *= g0 / (1.f + __expf(-g0));
                    v1 *= g1 / (1.f + __expf(-g1));
                    *(__half2*)(C16 + (size_t)rr * N + col) = __floats2half2_rn(v0, v1);
                } else {
                    *(float2*)(C + (size_t)rr * N + col) = make_float2(v0, v1);
                }
            }
        }
    }
}

// =====================================================================
// Fused QKV GEMM (fp16 core): B = concat[wq|wk|wv] (N=6144).
// Epilogue: RoPE + relayout; Q/K -> bf16 hi/lo for flash, K/V fp32 outputs.
// =====================================================================
__global__ void __launch_bounds__(256, 1) gemm_qkv(
    const __half* __restrict__ A16,
    const __half* __restrict__ Bhi, const __half* __restrict__ Blo,
    const float* __restrict__ bq, const float* __restrict__ bk, const float* __restrict__ bv,
    const float* __restrict__ cosb, const float* __restrict__ sinb,
    float* __restrict__ out_k, float* __restrict__ out_v,
    __nv_bfloat16* __restrict__ Qh, __nv_bfloat16* __restrict__ Ql,
    __nv_bfloat16* __restrict__ Kh, __nv_bfloat16* __restrict__ Kl,
    __nv_bfloat16* __restrict__ V16)
{
    extern __shared__ char smraw[];
    const uint32_t sb = smem_u32(smraw);
    const int tid = threadIdx.x;
    const int wid = tid >> 5;
    const int lane = tid & 31;
    const int wm = wid & 1;
    const int wn = wid >> 1;
    const int m0 = blockIdx.y * 128;
    const int n0 = blockIdx.x * 256;
    const int K = DIM;
    const int nk = K >> 5;
    const int lr = tid >> 2;
    const int lg = tid & 3;
    const int sec = n0 >> 11;
    const float* bias = (sec == 0) ? bq : ((sec == 1) ? bk : bv);

    float acc[4][8][4];
    #pragma unroll
    for (int a = 0; a < 4; a++)
        #pragma unroll
        for (int b = 0; b < 8; b++)
            #pragma unroll
            for (int c = 0; c < 4; c++) acc[a][b][c] = 0.f;

    GEMM_ISSUE_LAMBDA(A16, Bhi, Blo, m0, n0, K)
    gemm_mainloop(acc, sb, nk, wm, wn, lane, issue_stage);

    const int mb = m0 + wm * 64;
    const int nb = n0 + wn * 64;
    #pragma unroll
    for (int mi = 0; mi < 4; mi++) {
        #pragma unroll
        for (int j = 0; j < 8; j++) {
            const int row = mb + mi * 16 + (lane >> 2);
            const int col = nb + j * 8 + (lane & 3) * 2;
            const float b0 = bias[col & 2047], b1 = bias[(col & 2047) + 1];
            const int nc = col & 2047;
            const int h = nc >> 7;
            const int d = nc & 127;
            #pragma unroll
            for (int half = 0; half < 2; half++) {
                const int rr = row + half * 8;
                float v0 = acc[mi][j][half * 2 + 0] + b0;
                float v1 = acc[mi][j][half * 2 + 1] + b1;
                const int bi = rr >> 11;
                const int s = rr & 2047;
                if (sec < 2) {
                    const int i2 = d >> 1;
                    const float c = cosb[(PREV_LEN + s) * 64 + i2];
                    const float sn = sinb[(PREV_LEN + s) * 64 + i2];
                    const float r0 = v0 * c - v1 * sn;
                    const float r1 = v0 * sn + v1 * c;
                    if (sec == 0) {
                        split_store2(Qh, Ql,
                            ((size_t)(bi * HEADS + h) * S_LEN + s) * HD + d,
                            r0 * QK_SCALE, r1 * QK_SCALE);
                    } else {
                        const size_t off = ((size_t)(bi * HEADS + h) * T_LEN + PREV_LEN + s) * HD + d;
                        *(float2*)(out_k + off) = make_float2(r0, r1);
                        split_store2(Kh, Kl, off, r0, r1);
                    }
                } else {
                    const size_t off = ((size_t)(bi * HEADS + h) * T_LEN + PREV_LEN + s) * HD + d;
                    *(float2*)(out_v + off) = make_float2(v0, v1);
                    __nv_bfloat162 bb = __floats2bfloat162_rn(v0, v1);
                    *(__nv_bfloat162*)(V16 + off) = bb;
                }
            }
        }
    }
}

// ---------------- cache copies ----------------
__global__ __launch_bounds__(256) void copy_cache_k(
    const float* __restrict__ in, float* __restrict__ out,
    __nv_bfloat16* __restrict__ Kh, __nv_bfloat16* __restrict__ Kl)
{
    int idx = blockIdx.x * 256 + threadIdx.x;
    int bh  = idx >> 15;
    int rem = idx & 32767;
    float4 v = ((const float4*)in)[idx];
    size_t off4 = (size_t)bh * (T_LEN * HD / 4) + rem;
    ((float4*)out)[off4] = v;
    size_t off = off4 * 4;
    split_store2(Kh, Kl, off,     v.x, v.y);
    split_store2(Kh, Kl, off + 2, v.z, v.w);
}

__global__ __launch_bounds__(256) void copy_cache_v(
    const float* __restrict__ in, float* __restrict__ out,
    __nv_bfloat16* __restrict__ V16)
{
    int idx = blockIdx.x * 256 + threadIdx.x;
    int bh  = idx >> 15;
    int rem = idx & 32767;
    float4 v = ((const float4*)in)[idx];
    size_t off4 = (size_t)bh * (T_LEN * HD / 4) + rem;
    ((float4*)out)[off4] = v;
    __align__(8) __nv_bfloat16 bv[4];
    bv[0] = __float2bfloat16(v.x); bv[1] = __float2bfloat16(v.y);
    bv[2] = __float2bfloat16(v.z); bv[3] = __float2bfloat16(v.w);
    *(uint2*)(V16 + off4 * 4) = *(const uint2*)bv;
}

// =====================================================================
// HMMA flash attention (bf16 3-pass, proven). Output now single fp16.
// =====================================================================
#define FBM 128
#define FBN 64
#define F_OFF_QH 0
#define F_OFF_QL 32768
#define F_OFF_ST 65536
#define F_STAGE  49152
#define F_SMEM   (F_OFF_ST + 2 * F_STAGE)   // 163840

__device__ __forceinline__ uint32_t swz256(int r, int g) {
    return (uint32_t)((r << 8) + (((g ^ (r & 7)) & 15) << 4));
}

__global__ void __launch_bounds__(256) flash_mma(
    const __nv_bfloat16* __restrict__ Qh, const __nv_bfloat16* __restrict__ Ql,
    const __nv_bfloat16* __restrict__ Kh, const __nv_bfloat16* __restrict__ Kl,
    const __nv_bfloat16* __restrict__ V16,
    __half* __restrict__ O16)
{
    extern __shared__ char smraw[];
    const uint32_t sb = smem_u32(smraw);
    const int tid = threadIdx.x;
    const int wid = tid >> 5;
    const int lane = tid & 31;
    const int mtile = gridDim.x - 1 - blockIdx.x;
    const int bh = blockIdx.y;
    const int m0 = mtile * FBM;
    const int jend = (PREV_LEN + m0 + FBM) / FBN;
    const int mask_start = (PREV_LEN + m0) / FBN;

    {
        const size_t qo = ((size_t)bh * S_LEN + m0) * HD;
        for (int i = tid; i < 2048; i += 256) {
            int r = i >> 4, g = i & 15;
            uint32_t sw = swz256(r, g);
            cp_async16(sb + F_OFF_QH + sw, Qh + qo + (size_t)r * HD + g * 8);
            cp_async16(sb + F_OFF_QL + sw, Ql + qo + (size_t)r * HD + g * 8);
        }
        CP_COMMIT();
    }

    auto issue_kv = [&](int jt, int slot) {
        const uint32_t st = sb + F_OFF_ST + slot * F_STAGE;
        const size_t ko = ((size_t)bh * T_LEN + jt * FBN) * HD;
        for (int i = tid; i < 1024; i += 256) {
            int r = i >> 4, g = i & 15;
            uint32_t sw = swz256(r, g);
            size_t go = ko + (size_t)r * HD + g * 8;
            cp_async16(st + sw, Kh + go);
            cp_async16(st + 16384 + sw, Kl + go);
            cp_async16(st + 32768 + sw, V16 + go);
        }
    };
    issue_kv(0, 0); CP_COMMIT();
    issue_kv(1, 1); CP_COMMIT();

    float of[16][4];
    #pragma unroll
    for (int i = 0; i < 16; i++)
        #pragma unroll
        for (int j = 0; j < 4; j++) of[i][j] = 0.f;
    float mrow0 = -1e30f, mrow1 = -1e30f, lrow0 = 0.f, lrow1 = 0.f;

    const int arow = wid * 16 + (lane & 15);
    const int agr  = lane >> 4;

    for (int jt = 0; jt < jend; jt++) {
        CP_WAIT1();
        __syncthreads();
        const uint32_t st = sb + F_OFF_ST + (jt & 1) * F_STAGE;
        const int t0 = jt * FBN;

        float sf[8][4];
        #pragma unroll
        for (int i = 0; i < 8; i++)
            #pragma unroll
            for (int j = 0; j < 4; j++) sf[i][j] = 0.f;

        #pragma unroll
        for (int pass = 0; pass < 3; pass++) {
            const uint32_t qb = sb + (pass == 2 ? F_OFF_QL : F_OFF_QH);
            const uint32_t kb = st + (pass == 1 ? 16384 : 0);
            #pragma unroll
            for (int kt = 0; kt < 8; kt++) {
                uint32_t a[4];
                ldsm4(a, qb + swz256(arow, kt * 2 + agr));
                #pragma unroll
                for (int nb = 0; nb < 4; nb++) {
                    uint32_t b[4];
                    ldsm4(b, kb + swz256(nb * 16 + (lane & 15), kt * 2 + agr));
                    mma_bf16(sf[nb * 2 + 0], a, b[0], b[2]);
                    mma_bf16(sf[nb * 2 + 1], a, b[1], b[3]);
                }
            }
        }

        if (jt >= mask_start) {
            const int rb = m0 + wid * 16 + (lane >> 2);
            const int cb = t0 + (lane & 3) * 2;
            #pragma unroll
            for (int nt = 0; nt < 8; nt++) {
                const int c0 = cb + nt * 8;
                if (c0     > PREV_LEN + rb)     sf[nt][0] = -1e30f;
                if (c0 + 1 > PREV_LEN + rb)     sf[nt][1] = -1e30f;
                if (c0     > PREV_LEN + rb + 8) sf[nt][2] = -1e30f;
                if (c0 + 1 > PREV_LEN + rb + 8) sf[nt][3] = -1e30f;
            }
        }

        float mx0 = -1e30f, mx1 = -1e30f;
        #pragma unroll
        for (int nt = 0; nt < 8; nt++) {
            mx0 = fmaxf(mx0, fmaxf(sf[nt][0], sf[nt][1]));
            mx1 = fmaxf(mx1, fmaxf(sf[nt][2], sf[nt][3]));
        }
        mx0 = fmaxf(mx0, __shfl_xor_sync(0xFFFFFFFF, mx0, 1));
        mx0 = fmaxf(mx0, __shfl_xor_sync(0xFFFFFFFF, mx0, 2));
        mx1 = fmaxf(mx1, __shfl_xor_sync(0xFFFFFFFF, mx1, 1));
        mx1 = fmaxf(mx1, __shfl_xor_sync(0xFFFFFFFF, mx1, 2));
        const float nm0 = fmaxf(mrow0, mx0);
        const float nm1 = fmaxf(mrow1, mx1);
        const float al0 = __expf(mrow0 - nm0);
        const float al1 = __expf(mrow1 - nm1);
        mrow0 = nm0; mrow1 = nm1;

        float rs0 = 0.f, rs1 = 0.f;
        #pragma unroll
        for (int nt = 0; nt < 8; nt++) {
            sf[nt][0] = __expf(sf[nt][0] - nm0);
            sf[nt][1] = __expf(sf[nt][1] - nm0);
            sf[nt][2] = __expf(sf[nt][2] - nm1);
            sf[nt][3] = __expf(sf[nt][3] - nm1);
            rs0 += sf[nt][0] + sf[nt][1];
            rs1 += sf[nt][2] + sf[nt][3];
        }
        rs0 += __shfl_xor_sync(0xFFFFFFFF, rs0, 1);
        rs0 += __shfl_xor_sync(0xFFFFFFFF, rs0, 2);
        rs1 += __shfl_xor_sync(0xFFFFFFFF, rs1, 1);
        rs1 += __shfl_xor_sync(0xFFFFFFFF, rs1, 2);
        lrow0 = lrow0 * al0 + rs0;
        lrow1 = lrow1 * al1 + rs1;

        #pragma unroll
        for (int nt = 0; nt < 16; nt++) {
            of[nt][0] *= al0; of[nt][1] *= al0;
            of[nt][2] *= al1; of[nt][3] *= al1;
        }

        #pragma unroll
        for (int kt = 0; kt < 4; kt++) {
            uint32_t a[4];
            a[0] = pack_bf16(sf[2 * kt][0],     sf[2 * kt][1]);
            a[1] = pack_bf16(sf[2 * kt][2],     sf[2 * kt][3]);
            a[2] = pack_bf16(sf[2 * kt + 1][0], sf[2 * kt + 1][1]);
            a[3] = pack_bf16(sf[2 * kt + 1][2], sf[2 * kt + 1][3]);
            const int vrow = kt * 16 + ((lane >> 3) & 1) * 8 + (lane & 7);
            #pragma unroll
            for (int nb = 0; nb < 8; nb++) {
                uint32_t b[4];
                ldsm4t(b, st + 32768 + swz256(vrow, nb * 2 + ((lane >> 4) & 1)));
                mma_bf16(of[nb * 2 + 0], a, b[0], b[1]);
                mma_bf16(of[nb * 2 + 1], a, b[2], b[3]);
            }
        }

        __syncthreads();
        if (jt + 2 < jend) issue_kv(jt + 2, jt & 1);
        CP_COMMIT();
    }

    const float inv0 = 1.f / lrow0;
    const float inv1 = 1.f / lrow1;
    const int b = bh >> 4, h = bh & 15;
    const int r0 = m0 + wid * 16 + (lane >> 2);
    #pragma unroll
    for (int nt = 0; nt < 16; nt++) {
        const int gc = h * HD + nt * 8 + (lane & 3) * 2;
        *(__half2*)(O16 + (size_t)(b * S_LEN + r0) * DIM + gc) =
            __floats2half2_rn(of[nt][0] * inv0, of[nt][1] * inv0);
        *(__half2*)(O16 + (size_t)(b * S_LEN + r0 + 8) * DIM + gc) =
            __floats2half2_rn(of[nt][2] * inv1, of[nt][3] * inv1);
    }
}

// ---------------- launch ----------------
extern "C" void kernel_launch(void* const* d_in, const int* in_sizes, int n_in,
                              void* d_out, int out_size)
{
    const float* x          = (const float*)d_in[0];
    const float* k_cache    = (const float*)d_in[1];
    const float* v_cache    = (const float*)d_in[2];
    const float* attn_norm_w= (const float*)d_in[3];
    const float* ffn_norm_w = (const float*)d_in[4];
    const float* wq = (const float*)d_in[5];
    const float* bq = (const float*)d_in[6];
    const float* wk = (const float*)d_in[7];
    const float* bk = (const float*)d_in[8];
    const float* wv = (const float*)d_in[9];
    const float* bv = (const float*)d_in[10];
    const float* wo = (const float*)d_in[11];
    const float* bo = (const float*)d_in[12];
    const float* w_gate = (const float*)d_in[13];
    const float* b_gate = (const float*)d_in[14];
    const float* w_val  = (const float*)d_in[15];
    const float* b_val  = (const float*)d_in[16];
    const float* w_proj = (const float*)d_in[17];
    const float* b_proj = (const float*)d_in[18];
    const float* fcos   = (const float*)d_in[19];
    const float* fsin   = (const float*)d_in[20];

    float* out_x = (float*)d_out;
    float* out_k = out_x + OUT_X_ELEMS;
    float* out_v = out_k + OUT_KV_ELEMS;

    float *p_x1, *p_g;
    __half *p_hA16, *p_h216, *p_o16, *p_gt16;
    __nv_bfloat16 *p_q16h, *p_q16l, *p_k16h, *p_k16l, *p_v16;
    __half *p_wqkv_hi, *p_wqkv_lo, *p_wo_hi, *p_wo_lo;
    __half *p_wg_hi, *p_wg_lo, *p_wv2_hi, *p_wv2_lo, *p_wp_hi, *p_wp_lo;

    cudaGetSymbolAddress((void**)&p_x1, g_x1);
    cudaGetSymbolAddress((void**)&p_g,  g_g);
    cudaGetSymbolAddress((void**)&p_hA16, g_hA16);
    cudaGetSymbolAddress((void**)&p_h216, g_h216);
    cudaGetSymbolAddress((void**)&p_o16,  g_o16);
    cudaGetSymbolAddress((void**)&p_gt16, g_gt16);
    cudaGetSymbolAddress((void**)&p_q16h, g_q16h);
    cudaGetSymbolAddress((void**)&p_q16l, g_q16l);
    cudaGetSymbolAddress((void**)&p_k16h, g_k16h);
    cudaGetSymbolAddress((void**)&p_k16l, g_k16l);
    cudaGetSymbolAddress((void**)&p_v16,  g_v16);
    cudaGetSymbolAddress((void**)&p_wqkv_hi, g_wqkv_hi);
    cudaGetSymbolAddress((void**)&p_wqkv_lo, g_wqkv_lo);
    cudaGetSymbolAddress((void**)&p_wo_hi, g_wo_hi);
    cudaGetSymbolAddress((void**)&p_wo_lo, g_wo_lo);
    cudaGetSymbolAddress((void**)&p_wg_hi, g_wg_hi);
    cudaGetSymbolAddress((void**)&p_wg_lo, g_wg_lo);
    cudaGetSymbolAddress((void**)&p_wv2_hi, g_wv2_hi);
    cudaGetSymbolAddress((void**)&p_wv2_lo, g_wv2_lo);
    cudaGetSymbolAddress((void**)&p_wp_hi, g_wp_hi);
    cudaGetSymbolAddress((void**)&p_wp_lo, g_wp_lo);

    cudaFuncSetAttribute(gemm_mma<0>, cudaFuncAttributeMaxDynamicSharedMemorySize, GM_SMEM);
    cudaFuncSetAttribute(gemm_mma<1>, cudaFuncAttributeMaxDynamicSharedMemorySize, GM_SMEM);
    cudaFuncSetAttribute(gemm_mma<2>, cudaFuncAttributeMaxDynamicSharedMemorySize, GM_SMEM);
    cudaFuncSetAttribute(gemm_qkv,   cudaFuncAttributeMaxDynamicSharedMemorySize, GM_SMEM);
    cudaFuncSetAttribute(flash_mma, cudaFuncAttributeMaxDynamicSharedMemorySize, F_SMEM);

    // ---- weight conversion + transpose (grid: K/32, N/128) ----
    weight_conv_t<<<dim3(64, 16), 256>>>(wq, p_wqkv_hi,                p_wqkv_lo,                DIM, DIM);
    weight_conv_t<<<dim3(64, 16), 256>>>(wk, p_wqkv_hi + DIM * DIM,    p_wqkv_lo + DIM * DIM,    DIM, DIM);
    weight_conv_t<<<dim3(64, 16), 256>>>(wv, p_wqkv_hi + 2 * DIM * DIM,p_wqkv_lo + 2 * DIM * DIM,DIM, DIM);
    weight_conv_t<<<dim3(64, 16), 256>>>(wo, p_wo_hi, p_wo_lo, DIM, DIM);
    weight_conv_t<<<dim3(64, 64), 256>>>(w_gate, p_wg_hi,  p_wg_lo,  FF_DIM, DIM);
    weight_conv_t<<<dim3(64, 64), 256>>>(w_val,  p_wv2_hi, p_wv2_lo, FF_DIM, DIM);
    weight_conv_t<<<dim3(256, 16), 256>>>(w_proj, p_wp_hi, p_wp_lo, DIM, FF_DIM);

    // ---- attention block ----
    rmsnorm_h<<<ROWS, 256>>>(x, attn_norm_w, p_hA16);
    gemm_qkv<<<dim3(24, 32), 256, GM_SMEM>>>(
        p_hA16, p_wqkv_hi, p_wqkv_lo, bq, bk, bv, fcos, fsin,
        out_k, out_v, p_q16h, p_q16l, p_k16h, p_k16l, p_v16);

    copy_cache_k<<<4096, 256>>>(k_cache, out_k, p_k16h, p_k16l);
    copy_cache_v<<<4096, 256>>>(v_cache, out_v, p_v16);

    flash_mma<<<dim3(S_LEN / FBM, BATCH * HEADS), 256, F_SMEM>>>(
        p_q16h, p_q16l, p_k16h, p_k16l, p_v16, p_o16);

    gemm_mma<1><<<dim3(8, 32), 256, GM_SMEM>>>(
        p_o16, p_wo_hi, p_wo_lo, bo, x, p_x1, nullptr, ROWS, DIM, DIM);

    // ---- ffn block ----
    rmsnorm_h<<<ROWS, 256>>>(p_x1, ffn_norm_w, p_h216);
    gemm_mma<0><<<dim3(32, 32), 256, GM_SMEM>>>(
        p_h216, p_wg_hi, p_wg_lo, b_gate, nullptr, p_g, nullptr, ROWS, FF_DIM, DIM);
    gemm_mma<2><<<dim3(32, 32), 256, GM_SMEM>>>(
        p_h216, p_wv2_hi, p_wv2_lo, b_val, p_g, nullptr, p_gt16, ROWS, FF_DIM, DIM);
    gemm_mma<1><<<dim3(8, 32), 256, GM_SMEM>>>(
        p_gt16, p_wp_hi, p_wp_lo, b_proj, p_x1, out_x, nullptr, ROWS, DIM, FF_DIM);
}

// round 8
// speedup vs baseline: 1.4170x; 1.0324x over previous
#include <cuda_runtime.h>
#include <cuda_bf16.h>
#include <cuda_fp16.h>
#include <cstdint>

// ---------------- problem constants ----------------
#define BATCH 2
#define S_LEN 2048
#define PREV_LEN 1024
#define T_LEN 3072
#define DIM 2048
#define HEADS 16
#define HD 128
#define FF_DIM 8192
#define ROWS (BATCH * S_LEN)  // 4096
#define QK_SCALE 0.08838834764831845f

#define OUT_X_ELEMS  (BATCH * S_LEN * DIM)
#define OUT_KV_ELEMS (BATCH * HEADS * T_LEN * HD)

// ================= PTX helpers (portable sm_80+) ====
__device__ __forceinline__ uint32_t smem_u32(const void* p) {
    uint32_t a;
    asm("{ .reg .u64 t; cvta.to.shared.u64 t, %1; cvt.u32.u64 %0, t; }" : "=r"(a) : "l"(p));
    return a;
}
__device__ __forceinline__ void cp_async16(uint32_t smem, const void* g) {
    asm volatile("cp.async.cg.shared.global [%0], [%1], 16;" :: "r"(smem), "l"(g) : "memory");
}
#define CP_COMMIT() asm volatile("cp.async.commit_group;" ::: "memory")
#define CP_WAIT2()  asm volatile("cp.async.wait_group 2;" ::: "memory")
#define CP_WAIT1()  asm volatile("cp.async.wait_group 1;" ::: "memory")

__device__ __forceinline__ void ldsm4(uint32_t* r, uint32_t addr) {
    asm volatile("ldmatrix.sync.aligned.m8n8.x4.shared.b16 {%0,%1,%2,%3}, [%4];"
        : "=r"(r[0]), "=r"(r[1]), "=r"(r[2]), "=r"(r[3]) : "r"(addr));
}
__device__ __forceinline__ void ldsm4t(uint32_t* r, uint32_t addr) {
    asm volatile("ldmatrix.sync.aligned.m8n8.x4.trans.shared.b16 {%0,%1,%2,%3}, [%4];"
        : "=r"(r[0]), "=r"(r[1]), "=r"(r[2]), "=r"(r[3]) : "r"(addr));
}
__device__ __forceinline__ void mma_f16(float* c, const uint32_t* a, uint32_t b0, uint32_t b1) {
    asm volatile(
        "mma.sync.aligned.m16n8k16.row.col.f32.f16.f16.f32 "
        "{%0,%1,%2,%3}, {%4,%5,%6,%7}, {%8,%9}, {%0,%1,%2,%3};"
        : "+f"(c[0]), "+f"(c[1]), "+f"(c[2]), "+f"(c[3])
        : "r"(a[0]), "r"(a[1]), "r"(a[2]), "r"(a[3]), "r"(b0), "r"(b1));
}
__device__ __forceinline__ uint32_t pack_f16(float a, float b) {
    __half2 t = __floats2half2_rn(a, b);
    return *(uint32_t*)&t;
}
__device__ __forceinline__ void split_store2h(
    __half* Hi, __half* Lo, size_t off, float a, float b)
{
    __half ha = __float2half(a), hb = __float2half(b);
    __half2 hh; hh.x = ha; hh.y = hb;
    __half2 ll;
    ll.x = __float2half(a - __half2float(ha));
    ll.y = __float2half(b - __half2float(hb));
    *(__half2*)(Hi + off) = hh;
    *(__half2*)(Lo + off) = ll;
}

// ---------------- scratch (device globals) --------
__device__ float g_x1 [ROWS * DIM];
__device__ float g_g  [ROWS * FF_DIM];
// fp16 single activations (GEMM A operands)
__device__ __half g_hA16 [ROWS * DIM];
__device__ __half g_h216 [ROWS * DIM];
__device__ __half g_o16  [ROWS * DIM];
__device__ __half g_gt16 [ROWS * FF_DIM];
// fp16 attention operands (b,h,s/t,d)
__device__ __half g_q16  [ROWS * DIM];
__device__ __half g_k16h [OUT_KV_ELEMS];
__device__ __half g_k16l [OUT_KV_ELEMS];
__device__ __half g_v16  [OUT_KV_ELEMS];
// fp16 hi/lo transposed weights [N][K]
__device__ __half g_wqkv_hi[3 * DIM * DIM];
__device__ __half g_wqkv_lo[3 * DIM * DIM];
__device__ __half g_wo_hi [DIM * DIM];
__device__ __half g_wo_lo [DIM * DIM];
__device__ __half g_wg_hi [DIM * FF_DIM];
__device__ __half g_wg_lo [DIM * FF_DIM];
__device__ __half g_wv2_hi[DIM * FF_DIM];
__device__ __half g_wv2_lo[DIM * FF_DIM];
__device__ __half g_wp_hi [FF_DIM * DIM];
__device__ __half g_wp_lo [FF_DIM * DIM];

// =====================================================================
// Weight converter + transpose: W[K][N] fp32 -> Wt[N][K] fp16 hi/lo.
// =====================================================================
__global__ __launch_bounds__(256) void weight_conv_t(
    const float* __restrict__ W, __half* __restrict__ Thi,
    __half* __restrict__ Tlo, int N, int K)
{
    __shared__ float tile[32][133];
    const int k0 = blockIdx.x * 32, n0 = blockIdx.y * 128;
    const int tid = threadIdx.x;
    {
        const int kr = tid >> 3;
        const int nq = (tid & 7) * 16;
        const float* src = W + (size_t)(k0 + kr) * N + n0 + nq;
        #pragma unroll
        for (int u = 0; u < 4; u++) {
            float4 v = *(const float4*)(src + u * 4);
            tile[kr][nq + u * 4 + 0] = v.x;
            tile[kr][nq + u * 4 + 1] = v.y;
            tile[kr][nq + u * 4 + 2] = v.z;
            tile[kr][nq + u * 4 + 3] = v.w;
        }
    }
    __syncthreads();
    const int n = tid >> 1;
    const int q = tid & 1;
    __align__(16) __half hv[16], lv[16];
    #pragma unroll
    for (int u = 0; u < 16; u++) {
        float v = tile[q * 16 + u][n];
        __half h = __float2half(v);
        hv[u] = h;
        lv[u] = __float2half(v - __half2float(h));
    }
    const size_t off = (size_t)(n0 + n) * K + k0 + q * 16;
    *(uint4*)(Thi + off)     = *(const uint4*)(hv);
    *(uint4*)(Thi + off + 8) = *(const uint4*)(hv + 8);
    *(uint4*)(Tlo + off)     = *(const uint4*)(lv);
    *(uint4*)(Tlo + off + 8) = *(const uint4*)(lv + 8);
}

// =====================================================================
// rmsnorm -> single fp16 row-major
// =====================================================================
__global__ __launch_bounds__(256) void rmsnorm_h(
    const float* __restrict__ x, const float* __restrict__ w,
    __half* __restrict__ O16)
{
    __shared__ float red[256];
    const int tid = threadIdx.x;
    const int m = blockIdx.x;
    const float* xp = x + (size_t)m * DIM + tid * 8;
    float4 a = *(const float4*)xp;
    float4 b = *(const float4*)(xp + 4);
    float s = a.x*a.x + a.y*a.y + a.z*a.z + a.w*a.w
            + b.x*b.x + b.y*b.y + b.z*b.z + b.w*b.w;
    red[tid] = s;
    __syncthreads();
    #pragma unroll
    for (int off = 128; off > 0; off >>= 1) {
        if (tid < off) red[tid] += red[tid + off];
        __syncthreads();
    }
    float scale = rsqrtf(red[0] * (1.0f / DIM) + 1e-6f);
    const float* wp = w + tid * 8;
    float4 wa = *(const float4*)wp;
    float4 wb = *(const float4*)(wp + 4);
    float y[8];
    y[0] = a.x*scale*wa.x; y[1] = a.y*scale*wa.y; y[2] = a.z*scale*wa.z; y[3] = a.w*scale*wa.w;
    y[4] = b.x*scale*wb.x; y[5] = b.y*scale*wb.y; y[6] = b.z*scale*wb.z; y[7] = b.w*scale*wb.w;
    __align__(16) __half hv[8];
    #pragma unroll
    for (int j = 0; j < 8; j++) hv[j] = __float2half(y[j]);
    *(uint4*)(O16 + (size_t)m * DIM + tid * 8) = *(const uint4*)hv;
}

// =====================================================================
// fp16 one-sided-split GEMM core. CTA 128x256, warp 64x64, 8 warps,
// K-chunk 32, 4-stage cp.async. C = A@Bh + A@Bl.
// =====================================================================
#define GM_STAGES 4
#define GM_STAGE_BYTES 40960
#define GM_SMEM (GM_STAGES * GM_STAGE_BYTES)   // 163840
#define OFF_A  0
#define OFF_BH 8192
#define OFF_BL 24576

__device__ __forceinline__ uint32_t swz(int r, int g) {
    return (uint32_t)(r * 64 + ((g ^ ((r >> 1) & 3)) << 4));
}

template<typename IssueF>
__device__ __forceinline__ void gemm_mainloop(
    float (&acc)[4][8][4], uint32_t sb, int nk, int wm, int wn, int lane,
    IssueF issue_stage)
{
    issue_stage(0, 0); CP_COMMIT();
    issue_stage(1, 1); CP_COMMIT();
    issue_stage(2, 2); CP_COMMIT();

    for (int kc = 0; kc < nk; kc++) {
        CP_WAIT2();
        __syncthreads();
        if (kc + 3 < nk) issue_stage(kc + 3, (kc + 3) & 3);
        CP_COMMIT();

        const uint32_t st = sb + (kc & 3) * GM_STAGE_BYTES;
        #pragma unroll
        for (int h = 0; h < 2; h++) {
            uint32_t a[4][4];
            #pragma unroll
            for (int mi = 0; mi < 4; mi++) {
                const int r = wm * 64 + mi * 16 + (lane & 15);
                ldsm4(a[mi], st + OFF_A + swz(r, h * 2 + (lane >> 4)));
            }
            #pragma unroll
            for (int ng = 0; ng < 4; ng++) {
                uint32_t bh[4], bl[4];
                const int r = wn * 64 + ng * 16 + (lane & 15);
                const uint32_t sw = swz(r, h * 2 + (lane >> 4));
                ldsm4(bh, st + OFF_BH + sw);
                ldsm4(bl, st + OFF_BL + sw);
                #pragma unroll
                for (int mi = 0; mi < 4; mi++) {
                    mma_f16(acc[mi][ng * 2 + 0], a[mi], bh[0], bh[2]);
                    mma_f16(acc[mi][ng * 2 + 1], a[mi], bh[1], bh[3]);
                    mma_f16(acc[mi][ng * 2 + 0], a[mi], bl[0], bl[2]);
                    mma_f16(acc[mi][ng * 2 + 1], a[mi], bl[1], bl[3]);
                }
            }
        }
        __syncthreads();
    }
}

#define GEMM_ISSUE_LAMBDA(A16, Bhi, Blo, m0, n0, K)                             \
    auto issue_stage = [&](int kc, int slot) {                                  \
        const uint32_t st = sb + slot * GM_STAGE_BYTES;                         \
        const int kelem = kc * 32 + lg * 8;                                     \
        _Pragma("unroll")                                                       \
        for (int i = 0; i < 2; i++) {                                           \
            const int r = lr + i * 64;                                          \
            cp_async16(st + OFF_A + swz(r, lg), A16 + (size_t)(m0 + r) * K + kelem); \
        }                                                                       \
        _Pragma("unroll")                                                       \
        for (int i = 0; i < 4; i++) {                                           \
            const int r = lr + i * 64;                                          \
            const uint32_t sw = swz(r, lg);                                     \
            cp_async16(st + OFF_BH + sw, Bhi + (size_t)(n0 + r) * K + kelem);   \
            cp_async16(st + OFF_BL + sw, Blo + (size_t)(n0 + r) * K + kelem);   \
        }                                                                       \
    };

// =====================================================================
// Generic GEMM: MODE 0: C=A@B+bias; 1: +extra (fp32 out);
//               2: silu(extra)*(A@B+bias) -> fp16 out C16
// =====================================================================
template<int MODE>
__global__ void __launch_bounds__(256, 1) gemm_mma(
    const __half* __restrict__ A16,
    const __half* __restrict__ Bhi, const __half* __restrict__ Blo,
    const float* __restrict__ bias, const float* __restrict__ extra,
    float* __restrict__ C, __half* __restrict__ C16,
    int M, int N, int K)
{
    extern __shared__ char smraw[];
    const uint32_t sb = smem_u32(smraw);
    const int tid = threadIdx.x;
    const int wid = tid >> 5;
    const int lane = tid & 31;
    const int wm = wid & 1;
    const int wn = wid >> 1;
    const int m0 = blockIdx.y * 128;
    const int n0 = blockIdx.x * 256;
    const int nk = K >> 5;
    const int lr = tid >> 2;
    const int lg = tid & 3;

    float acc[4][8][4];
    #pragma unroll
    for (int a = 0; a < 4; a++)
        #pragma unroll
        for (int b = 0; b < 8; b++)
            #pragma unroll
            for (int c = 0; c < 4; c++) acc[a][b][c] = 0.f;

    GEMM_ISSUE_LAMBDA(A16, Bhi, Blo, m0, n0, K)
    gemm_mainloop(acc, sb, nk, wm, wn, lane, issue_stage);

    const int mb = m0 + wm * 64;
    const int nb = n0 + wn * 64;
    #pragma unroll
    for (int mi = 0; mi < 4; mi++) {
        #pragma unroll
        for (int j = 0; j < 8; j++) {
            const int row = mb + mi * 16 + (lane >> 2);
            const int col = nb + j * 8 + (lane & 3) * 2;
            const float b0 = bias[col], b1 = bias[col + 1];
            #pragma unroll
            for (int half = 0; half < 2; half++) {
                const int rr = row + half * 8;
                float v0 = acc[mi][j][half * 2 + 0] + b0;
                float v1 = acc[mi][j][half * 2 + 1] + b1;
                if (MODE == 1) {
                    const float* ep = extra + (size_t)rr * N + col;
                    v0 += ep[0]; v1 += ep[1];
                }
                if (MODE == 2) {
                    const float* ep = extra + (size_t)rr * N + col;
                    float g0 = ep[0], g1 = ep[1];
                    v0 *= g0 / (1.f + __expf(-g0));
                    v1 *= g1 / (1.f + __expf(-g1));
                    *(__half2*)(C16 + (size_t)rr * N + col) = __floats2half2_rn(v0, v1);
                } else {
                    *(float2*)(C + (size_t)rr * N + col) = make_float2(v0, v1);
                }
            }
        }
    }
}

// =====================================================================
// Fused QKV GEMM (fp16 core): B = concat[wq|wk|wv] (N=6144).
// Epilogue: RoPE + relayout. Q -> single fp16; K -> fp32 + fp16 hi/lo;
// V -> fp32 + fp16.
// =====================================================================
__global__ void __launch_bounds__(256, 1) gemm_qkv(
    const __half* __restrict__ A16,
    const __half* __restrict__ Bhi, const __half* __restrict__ Blo,
    const float* __restrict__ bq, const float* __restrict__ bk, const float* __restrict__ bv,
    const float* __restrict__ cosb, const float* __restrict__ sinb,
    float* __restrict__ out_k, float* __restrict__ out_v,
    __half* __restrict__ Q16,
    __half* __restrict__ Kh, __half* __restrict__ Kl,
    __half* __restrict__ V16)
{
    extern __shared__ char smraw[];
    const uint32_t sb = smem_u32(smraw);
    const int tid = threadIdx.x;
    const int wid = tid >> 5;
    const int lane = tid & 31;
    const int wm = wid & 1;
    const int wn = wid >> 1;
    const int m0 = blockIdx.y * 128;
    const int n0 = blockIdx.x * 256;
    const int K = DIM;
    const int nk = K >> 5;
    const int lr = tid >> 2;
    const int lg = tid & 3;
    const int sec = n0 >> 11;
    const float* bias = (sec == 0) ? bq : ((sec == 1) ? bk : bv);

    float acc[4][8][4];
    #pragma unroll
    for (int a = 0; a < 4; a++)
        #pragma unroll
        for (int b = 0; b < 8; b++)
            #pragma unroll
            for (int c = 0; c < 4; c++) acc[a][b][c] = 0.f;

    GEMM_ISSUE_LAMBDA(A16, Bhi, Blo, m0, n0, K)
    gemm_mainloop(acc, sb, nk, wm, wn, lane, issue_stage);

    const int mb = m0 + wm * 64;
    const int nb = n0 + wn * 64;
    #pragma unroll
    for (int mi = 0; mi < 4; mi++) {
        #pragma unroll
        for (int j = 0; j < 8; j++) {
            const int row = mb + mi * 16 + (lane >> 2);
            const int col = nb + j * 8 + (lane & 3) * 2;
            const float b0 = bias[col & 2047], b1 = bias[(col & 2047) + 1];
            const int nc = col & 2047;
            const int h = nc >> 7;
            const int d = nc & 127;
            #pragma unroll
            for (int half = 0; half < 2; half++) {
                const int rr = row + half * 8;
                float v0 = acc[mi][j][half * 2 + 0] + b0;
                float v1 = acc[mi][j][half * 2 + 1] + b1;
                const int bi = rr >> 11;
                const int s = rr & 2047;
                if (sec < 2) {
                    const int i2 = d >> 1;
                    const float c = cosb[(PREV_LEN + s) * 64 + i2];
                    const float sn = sinb[(PREV_LEN + s) * 64 + i2];
                    const float r0 = v0 * c - v1 * sn;
                    const float r1 = v0 * sn + v1 * c;
                    if (sec == 0) {
                        *(__half2*)(Q16 + ((size_t)(bi * HEADS + h) * S_LEN + s) * HD + d) =
                            __floats2half2_rn(r0 * QK_SCALE, r1 * QK_SCALE);
                    } else {
                        const size_t off = ((size_t)(bi * HEADS + h) * T_LEN + PREV_LEN + s) * HD + d;
                        *(float2*)(out_k + off) = make_float2(r0, r1);
                        split_store2h(Kh, Kl, off, r0, r1);
                    }
                } else {
                    const size_t off = ((size_t)(bi * HEADS + h) * T_LEN + PREV_LEN + s) * HD + d;
                    *(float2*)(out_v + off) = make_float2(v0, v1);
                    *(__half2*)(V16 + off) = __floats2half2_rn(v0, v1);
                }
            }
        }
    }
}

// ---------------- cache copies ----------------
__global__ __launch_bounds__(256) void copy_cache_k(
    const float* __restrict__ in, float* __restrict__ out,
    __half* __restrict__ Kh, __half* __restrict__ Kl)
{
    int idx = blockIdx.x * 256 + threadIdx.x;
    int bh  = idx >> 15;
    int rem = idx & 32767;
    float4 v = ((const float4*)in)[idx];
    size_t off4 = (size_t)bh * (T_LEN * HD / 4) + rem;
    ((float4*)out)[off4] = v;
    size_t off = off4 * 4;
    split_store2h(Kh, Kl, off,     v.x, v.y);
    split_store2h(Kh, Kl, off + 2, v.z, v.w);
}

__global__ __launch_bounds__(256) void copy_cache_v(
    const float* __restrict__ in, float* __restrict__ out,
    __half* __restrict__ V16)
{
    int idx = blockIdx.x * 256 + threadIdx.x;
    int bh  = idx >> 15;
    int rem = idx & 32767;
    float4 v = ((const float4*)in)[idx];
    size_t off4 = (size_t)bh * (T_LEN * HD / 4) + rem;
    ((float4*)out)[off4] = v;
    __align__(8) __half bv[4];
    bv[0] = __float2half(v.x); bv[1] = __float2half(v.y);
    bv[2] = __float2half(v.z); bv[3] = __float2half(v.w);
    *(uint2*)(V16 + off4 * 4) = *(const uint2*)bv;
}

// =====================================================================
// HMMA flash attention, fp16 2-pass:
// S = Q·Kh + Q·Kl (Q single fp16), P·V fp16.
// smem: Q 32K | stage{0,1}: Kh 16K, Kl 16K, V 16K.
// =====================================================================
#define FBM 128
#define FBN 64
#define F_OFF_Q  0
#define F_OFF_ST 32768
#define F_STAGE  49152
#define F_SMEM   (F_OFF_ST + 2 * F_STAGE)   // 131072

__device__ __forceinline__ uint32_t swz256(int r, int g) {
    return (uint32_t)((r << 8) + (((g ^ (r & 7)) & 15) << 4));
}

__global__ void __launch_bounds__(256) flash_mma(
    const __half* __restrict__ Q16,
    const __half* __restrict__ Kh, const __half* __restrict__ Kl,
    const __half* __restrict__ V16,
    __half* __restrict__ O16)
{
    extern __shared__ char smraw[];
    const uint32_t sb = smem_u32(smraw);
    const int tid = threadIdx.x;
    const int wid = tid >> 5;
    const int lane = tid & 31;
    const int mtile = gridDim.x - 1 - blockIdx.x;
    const int bh = blockIdx.y;
    const int m0 = mtile * FBM;
    const int jend = (PREV_LEN + m0 + FBM) / FBN;
    const int mask_start = (PREV_LEN + m0) / FBN;

    {
        const size_t qo = ((size_t)bh * S_LEN + m0) * HD;
        for (int i = tid; i < 2048; i += 256) {
            int r = i >> 4, g = i & 15;
            cp_async16(sb + F_OFF_Q + swz256(r, g), Q16 + qo + (size_t)r * HD + g * 8);
        }
        CP_COMMIT();
    }

    auto issue_kv = [&](int jt, int slot) {
        const uint32_t st = sb + F_OFF_ST + slot * F_STAGE;
        const size_t ko = ((size_t)bh * T_LEN + jt * FBN) * HD;
        for (int i = tid; i < 1024; i += 256) {
            int r = i >> 4, g = i & 15;
            uint32_t sw = swz256(r, g);
            size_t go = ko + (size_t)r * HD + g * 8;
            cp_async16(st + sw, Kh + go);
            cp_async16(st + 16384 + sw, Kl + go);
            cp_async16(st + 32768 + sw, V16 + go);
        }
    };
    issue_kv(0, 0); CP_COMMIT();
    issue_kv(1, 1); CP_COMMIT();

    float of[16][4];
    #pragma unroll
    for (int i = 0; i < 16; i++)
        #pragma unroll
        for (int j = 0; j < 4; j++) of[i][j] = 0.f;
    float mrow0 = -1e30f, mrow1 = -1e30f, lrow0 = 0.f, lrow1 = 0.f;

    const int arow = wid * 16 + (lane & 15);
    const int agr  = lane >> 4;

    for (int jt = 0; jt < jend; jt++) {
        CP_WAIT1();
        __syncthreads();
        const uint32_t st = sb + F_OFF_ST + (jt & 1) * F_STAGE;
        const int t0 = jt * FBN;

        float sf[8][4];
        #pragma unroll
        for (int i = 0; i < 8; i++)
            #pragma unroll
            for (int j = 0; j < 4; j++) sf[i][j] = 0.f;

        #pragma unroll
        for (int kt = 0; kt < 8; kt++) {
            uint32_t a[4];
            ldsm4(a, sb + F_OFF_Q + swz256(arow, kt * 2 + agr));
            #pragma unroll
            for (int pass = 0; pass < 2; pass++) {
                const uint32_t kb = st + pass * 16384;
                #pragma unroll
                for (int nb = 0; nb < 4; nb++) {
                    uint32_t b[4];
                    ldsm4(b, kb + swz256(nb * 16 + (lane & 15), kt * 2 + agr));
                    mma_f16(sf[nb * 2 + 0], a, b[0], b[2]);
                    mma_f16(sf[nb * 2 + 1], a, b[1], b[3]);
                }
            }
        }

        if (jt >= mask_start) {
            const int rb = m0 + wid * 16 + (lane >> 2);
            const int cb = t0 + (lane & 3) * 2;
            #pragma unroll
            for (int nt = 0; nt < 8; nt++) {
                const int c0 = cb + nt * 8;
                if (c0     > PREV_LEN + rb)     sf[nt][0] = -1e30f;
                if (c0 + 1 > PREV_LEN + rb)     sf[nt][1] = -1e30f;
                if (c0     > PREV_LEN + rb + 8) sf[nt][2] = -1e30f;
                if (c0 + 1 > PREV_LEN + rb + 8) sf[nt][3] = -1e30f;
            }
        }

        float mx0 = -1e30f, mx1 = -1e30f;
        #pragma unroll
        for (int nt = 0; nt < 8; nt++) {
            mx0 = fmaxf(mx0, fmaxf(sf[nt][0], sf[nt][1]));
            mx1 = fmaxf(mx1, fmaxf(sf[nt][2], sf[nt][3]));
        }
        mx0 = fmaxf(mx0, __shfl_xor_sync(0xFFFFFFFF, mx0, 1));
        mx0 = fmaxf(mx0, __shfl_xor_sync(0xFFFFFFFF, mx0, 2));
        mx1 = fmaxf(mx1, __shfl_xor_sync(0xFFFFFFFF, mx1, 1));
        mx1 = fmaxf(mx1, __shfl_xor_sync(0xFFFFFFFF, mx1, 2));
        const float nm0 = fmaxf(mrow0, mx0);
        const float nm1 = fmaxf(mrow1, mx1);
        const float al0 = __expf(mrow0 - nm0);
        const float al1 = __expf(mrow1 - nm1);
        mrow0 = nm0; mrow1 = nm1;

        float rs0 = 0.f, rs1 = 0.f;
        #pragma unroll
        for (int nt = 0; nt < 8; nt++) {
            sf[nt][0] = __expf(sf[nt][0] - nm0);
            sf[nt][1] = __expf(sf[nt][1] - nm0);
            sf[nt][2] = __expf(sf[nt][2] - nm1);
            sf[nt][3] = __expf(sf[nt][3] - nm1);
            rs0 += sf[nt][0] + sf[nt][1];
            rs1 += sf[nt][2] + sf[nt][3];
        }
        rs0 += __shfl_xor_sync(0xFFFFFFFF, rs0, 1);
        rs0 += __shfl_xor_sync(0xFFFFFFFF, rs0, 2);
        rs1 += __shfl_xor_sync(0xFFFFFFFF, rs1, 1);
        rs1 += __shfl_xor_sync(0xFFFFFFFF, rs1, 2);
        lrow0 = lrow0 * al0 + rs0;
        lrow1 = lrow1 * al1 + rs1;

        #pragma unroll
        for (int nt = 0; nt < 16; nt++) {
            of[nt][0] *= al0; of[nt][1] *= al0;
            of[nt][2] *= al1; of[nt][3] *= al1;
        }

        #pragma unroll
        for (int kt = 0; kt < 4; kt++) {
            uint32_t a[4];
            a[0] = pack_f16(sf[2 * kt][0],     sf[2 * kt][1]);
            a[1] = pack_f16(sf[2 * kt][2],     sf[2 * kt][3]);
            a[2] = pack_f16(sf[2 * kt + 1][0], sf[2 * kt + 1][1]);
            a[3] = pack_f16(sf[2 * kt + 1][2], sf[2 * kt + 1][3]);
            const int vrow = kt * 16 + ((lane >> 3) & 1) * 8 + (lane & 7);
            #pragma unroll
            for (int nb = 0; nb < 8; nb++) {
                uint32_t b[4];
                ldsm4t(b, st + 32768 + swz256(vrow, nb * 2 + ((lane >> 4) & 1)));
                mma_f16(of[nb * 2 + 0], a, b[0], b[1]);
                mma_f16(of[nb * 2 + 1], a, b[2], b[3]);
            }
        }

        __syncthreads();
        if (jt + 2 < jend) issue_kv(jt + 2, jt & 1);
        CP_COMMIT();
    }

    const float inv0 = 1.f / lrow0;
    const float inv1 = 1.f / lrow1;
    const int b = bh >> 4, h = bh & 15;
    const int r0 = m0 + wid * 16 + (lane >> 2);
    #pragma unroll
    for (int nt = 0; nt < 16; nt++) {
        const int gc = h * HD + nt * 8 + (lane & 3) * 2;
        *(__half2*)(O16 + (size_t)(b * S_LEN + r0) * DIM + gc) =
            __floats2half2_rn(of[nt][0] * inv0, of[nt][1] * inv0);
        *(__half2*)(O16 + (size_t)(b * S_LEN + r0 + 8) * DIM + gc) =
            __floats2half2_rn(of[nt][2] * inv1, of[nt][3] * inv1);
    }
}

// ---------------- launch ----------------
extern "C" void kernel_launch(void* const* d_in, const int* in_sizes, int n_in,
                              void* d_out, int out_size)
{
    const float* x          = (const float*)d_in[0];
    const float* k_cache    = (const float*)d_in[1];
    const float* v_cache    = (const float*)d_in[2];
    const float* attn_norm_w= (const float*)d_in[3];
    const float* ffn_norm_w = (const float*)d_in[4];
    const float* wq = (const float*)d_in[5];
    const float* bq = (const float*)d_in[6];
    const float* wk = (const float*)d_in[7];
    const float* bk = (const float*)d_in[8];
    const float* wv = (const float*)d_in[9];
    const float* bv = (const float*)d_in[10];
    const float* wo = (const float*)d_in[11];
    const float* bo = (const float*)d_in[12];
    const float* w_gate = (const float*)d_in[13];
    const float* b_gate = (const float*)d_in[14];
    const float* w_val  = (const float*)d_in[15];
    const float* b_val  = (const float*)d_in[16];
    const float* w_proj = (const float*)d_in[17];
    const float* b_proj = (const float*)d_in[18];
    const float* fcos   = (const float*)d_in[19];
    const float* fsin   = (const float*)d_in[20];

    float* out_x = (float*)d_out;
    float* out_k = out_x + OUT_X_ELEMS;
    float* out_v = out_k + OUT_KV_ELEMS;

    float *p_x1, *p_g;
    __half *p_hA16, *p_h216, *p_o16, *p_gt16;
    __half *p_q16, *p_k16h, *p_k16l, *p_v16;
    __half *p_wqkv_hi, *p_wqkv_lo, *p_wo_hi, *p_wo_lo;
    __half *p_wg_hi, *p_wg_lo, *p_wv2_hi, *p_wv2_lo, *p_wp_hi, *p_wp_lo;

    cudaGetSymbolAddress((void**)&p_x1, g_x1);
    cudaGetSymbolAddress((void**)&p_g,  g_g);
    cudaGetSymbolAddress((void**)&p_hA16, g_hA16);
    cudaGetSymbolAddress((void**)&p_h216, g_h216);
    cudaGetSymbolAddress((void**)&p_o16,  g_o16);
    cudaGetSymbolAddress((void**)&p_gt16, g_gt16);
    cudaGetSymbolAddress((void**)&p_q16,  g_q16);
    cudaGetSymbolAddress((void**)&p_k16h, g_k16h);
    cudaGetSymbolAddress((void**)&p_k16l, g_k16l);
    cudaGetSymbolAddress((void**)&p_v16,  g_v16);
    cudaGetSymbolAddress((void**)&p_wqkv_hi, g_wqkv_hi);
    cudaGetSymbolAddress((void**)&p_wqkv_lo, g_wqkv_lo);
    cudaGetSymbolAddress((void**)&p_wo_hi, g_wo_hi);
    cudaGetSymbolAddress((void**)&p_wo_lo, g_wo_lo);
    cudaGetSymbolAddress((void**)&p_wg_hi, g_wg_hi);
    cudaGetSymbolAddress((void**)&p_wg_lo, g_wg_lo);
    cudaGetSymbolAddress((void**)&p_wv2_hi, g_wv2_hi);
    cudaGetSymbolAddress((void**)&p_wv2_lo, g_wv2_lo);
    cudaGetSymbolAddress((void**)&p_wp_hi, g_wp_hi);
    cudaGetSymbolAddress((void**)&p_wp_lo, g_wp_lo);

    cudaFuncSetAttribute(gemm_mma<0>, cudaFuncAttributeMaxDynamicSharedMemorySize, GM_SMEM);
    cudaFuncSetAttribute(gemm_mma<1>, cudaFuncAttributeMaxDynamicSharedMemorySize, GM_SMEM);
    cudaFuncSetAttribute(gemm_mma<2>, cudaFuncAttributeMaxDynamicSharedMemorySize, GM_SMEM);
    cudaFuncSetAttribute(gemm_qkv,   cudaFuncAttributeMaxDynamicSharedMemorySize, GM_SMEM);
    cudaFuncSetAttribute(flash_mma, cudaFuncAttributeMaxDynamicSharedMemorySize, F_SMEM);

    // ---- weight conversion + transpose (grid: K/32, N/128) ----
    weight_conv_t<<<dim3(64, 16), 256>>>(wq, p_wqkv_hi,                p_wqkv_lo,                DIM, DIM);
    weight_conv_t<<<dim3(64, 16), 256>>>(wk, p_wqkv_hi + DIM * DIM,    p_wqkv_lo + DIM * DIM,    DIM, DIM);
    weight_conv_t<<<dim3(64, 16), 256>>>(wv, p_wqkv_hi + 2 * DIM * DIM,p_wqkv_lo + 2 * DIM * DIM,DIM, DIM);
    weight_conv_t<<<dim3(64, 16), 256>>>(wo, p_wo_hi, p_wo_lo, DIM, DIM);
    weight_conv_t<<<dim3(64, 64), 256>>>(w_gate, p_wg_hi,  p_wg_lo,  FF_DIM, DIM);
    weight_conv_t<<<dim3(64, 64), 256>>>(w_val,  p_wv2_hi, p_wv2_lo, FF_DIM, DIM);
    weight_conv_t<<<dim3(256, 16), 256>>>(w_proj, p_wp_hi, p_wp_lo, DIM, FF_DIM);

    // ---- attention block ----
    rmsnorm_h<<<ROWS, 256>>>(x, attn_norm_w, p_hA16);
    gemm_qkv<<<dim3(24, 32), 256, GM_SMEM>>>(
        p_hA16, p_wqkv_hi, p_wqkv_lo, bq, bk, bv, fcos, fsin,
        out_k, out_v, p_q16, p_k16h, p_k16l, p_v16);

    copy_cache_k<<<4096, 256>>>(k_cache, out_k, p_k16h, p_k16l);
    copy_cache_v<<<4096, 256>>>(v_cache, out_v, p_v16);

    flash_mma<<<dim3(S_LEN / FBM, BATCH * HEADS), 256, F_SMEM>>>(
        p_q16, p_k16h, p_k16l, p_v16, p_o16);

    gemm_mma<1><<<dim3(8, 32), 256, GM_SMEM>>>(
        p_o16, p_wo_hi, p_wo_lo, bo, x, p_x1, nullptr, ROWS, DIM, DIM);

    // ---- ffn block ----
    rmsnorm_h<<<ROWS, 256>>>(p_x1, ffn_norm_w, p_h216);
    gemm_mma<0><<<dim3(32, 32), 256, GM_SMEM>>>(
        p_h216, p_wg_hi, p_wg_lo, b_gate, nullptr, p_g, nullptr, ROWS, FF_DIM, DIM);
    gemm_mma<2><<<dim3(32, 32), 256, GM_SMEM>>>(
        p_h216, p_wv2_hi, p_wv2_lo, b_val, p_g, nullptr, p_gt16, ROWS, FF_DIM, DIM);
    gemm_mma<1><<<dim3(8, 32), 256, GM_SMEM>>>(
        p_gt16, p_wp_hi, p_wp_lo, b_proj, p_x1, out_x, nullptr, ROWS, DIM, FF_DIM);
}

// round 9
// speedup vs baseline: 2.3619x; 1.6668x over previous
#include <cuda_runtime.h>
#include <cuda_bf16.h>
#include <cuda_fp16.h>
#include <cstdint>

// ---------------- problem constants ----------------
#define BATCH 2
#define S_LEN 2048
#define PREV_LEN 1024
#define T_LEN 3072
#define DIM 2048
#define HEADS 16
#define HD 128
#define FF_DIM 8192
#define ROWS (BATCH * S_LEN)  // 4096
#define QK_SCALE 0.08838834764831845f

#define OUT_X_ELEMS  (BATCH * S_LEN * DIM)
#define OUT_KV_ELEMS (BATCH * HEADS * T_LEN * HD)

// ================= PTX helpers (portable sm_80+) ====
__device__ __forceinline__ uint32_t smem_u32(const void* p) {
    uint32_t a;
    asm("{ .reg .u64 t; cvta.to.shared.u64 t, %1; cvt.u32.u64 %0, t; }" : "=r"(a) : "l"(p));
    return a;
}
__device__ __forceinline__ void cp_async16(uint32_t smem, const void* g) {
    asm volatile("cp.async.cg.shared.global [%0], [%1], 16;" :: "r"(smem), "l"(g) : "memory");
}
#define CP_COMMIT() asm volatile("cp.async.commit_group;" ::: "memory")
#define CP_WAIT6()  asm volatile("cp.async.wait_group 6;" ::: "memory")
#define CP_WAIT1()  asm volatile("cp.async.wait_group 1;" ::: "memory")

__device__ __forceinline__ void ldsm4(uint32_t* r, uint32_t addr) {
    asm volatile("ldmatrix.sync.aligned.m8n8.x4.shared.b16 {%0,%1,%2,%3}, [%4];"
        : "=r"(r[0]), "=r"(r[1]), "=r"(r[2]), "=r"(r[3]) : "r"(addr));
}
__device__ __forceinline__ void ldsm4t(uint32_t* r, uint32_t addr) {
    asm volatile("ldmatrix.sync.aligned.m8n8.x4.trans.shared.b16 {%0,%1,%2,%3}, [%4];"
        : "=r"(r[0]), "=r"(r[1]), "=r"(r[2]), "=r"(r[3]) : "r"(addr));
}
__device__ __forceinline__ void mma_f16(float* c, const uint32_t* a, uint32_t b0, uint32_t b1) {
    asm volatile(
        "mma.sync.aligned.m16n8k16.row.col.f32.f16.f16.f32 "
        "{%0,%1,%2,%3}, {%4,%5,%6,%7}, {%8,%9}, {%0,%1,%2,%3};"
        : "+f"(c[0]), "+f"(c[1]), "+f"(c[2]), "+f"(c[3])
        : "r"(a[0]), "r"(a[1]), "r"(a[2]), "r"(a[3]), "r"(b0), "r"(b1));
}
__device__ __forceinline__ uint32_t pack_f16(float a, float b) {
    __half2 t = __floats2half2_rn(a, b);
    return *(uint32_t*)&t;
}

// ---------------- scratch (device globals) --------
__device__ float g_x1 [ROWS * DIM];
__device__ float g_g  [ROWS * FF_DIM];
// fp16 single activations (GEMM A operands)
__device__ __half g_hA16 [ROWS * DIM];
__device__ __half g_h216 [ROWS * DIM];
__device__ __half g_o16  [ROWS * DIM];
__device__ __half g_gt16 [ROWS * FF_DIM];
// fp16 attention operands (b,h,s/t,d)
__device__ __half g_q16 [ROWS * DIM];
__device__ __half g_k16 [OUT_KV_ELEMS];
__device__ __half g_v16 [OUT_KV_ELEMS];
// fp16 transposed weights [N][K]
__device__ __half g_wqkv[3 * DIM * DIM];
__device__ __half g_wo  [DIM * DIM];
__device__ __half g_wg  [DIM * FF_DIM];
__device__ __half g_wv2 [DIM * FF_DIM];
__device__ __half g_wp  [FF_DIM * DIM];

// =====================================================================
// Weight converter + transpose: W[K][N] fp32 -> Wt[N][K] fp16.
// grid (K/32, N/128), 256 threads.
// =====================================================================
__global__ __launch_bounds__(256) void weight_conv_t(
    const float* __restrict__ W, __half* __restrict__ T16, int N, int K)
{
    __shared__ float tile[32][133];
    const int k0 = blockIdx.x * 32, n0 = blockIdx.y * 128;
    const int tid = threadIdx.x;
    {
        const int kr = tid >> 3;
        const int nq = (tid & 7) * 16;
        const float* src = W + (size_t)(k0 + kr) * N + n0 + nq;
        #pragma unroll
        for (int u = 0; u < 4; u++) {
            float4 v = *(const float4*)(src + u * 4);
            tile[kr][nq + u * 4 + 0] = v.x;
            tile[kr][nq + u * 4 + 1] = v.y;
            tile[kr][nq + u * 4 + 2] = v.z;
            tile[kr][nq + u * 4 + 3] = v.w;
        }
    }
    __syncthreads();
    const int n = tid >> 1;
    const int q = tid & 1;
    __align__(16) __half hv[16];
    #pragma unroll
    for (int u = 0; u < 16; u++)
        hv[u] = __float2half(tile[q * 16 + u][n]);
    const size_t off = (size_t)(n0 + n) * K + k0 + q * 16;
    *(uint4*)(T16 + off)     = *(const uint4*)(hv);
    *(uint4*)(T16 + off + 8) = *(const uint4*)(hv + 8);
}

// =====================================================================
// rmsnorm -> single fp16 row-major
// =====================================================================
__global__ __launch_bounds__(256) void rmsnorm_h(
    const float* __restrict__ x, const float* __restrict__ w,
    __half* __restrict__ O16)
{
    __shared__ float red[256];
    const int tid = threadIdx.x;
    const int m = blockIdx.x;
    const float* xp = x + (size_t)m * DIM + tid * 8;
    float4 a = *(const float4*)xp;
    float4 b = *(const float4*)(xp + 4);
    float s = a.x*a.x + a.y*a.y + a.z*a.z + a.w*a.w
            + b.x*b.x + b.y*b.y + b.z*b.z + b.w*b.w;
    red[tid] = s;
    __syncthreads();
    #pragma unroll
    for (int off = 128; off > 0; off >>= 1) {
        if (tid < off) red[tid] += red[tid + off];
        __syncthreads();
    }
    float scale = rsqrtf(red[0] * (1.0f / DIM) + 1e-6f);
    const float* wp = w + tid * 8;
    float4 wa = *(const float4*)wp;
    float4 wb = *(const float4*)(wp + 4);
    float y[8];
    y[0] = a.x*scale*wa.x; y[1] = a.y*scale*wa.y; y[2] = a.z*scale*wa.z; y[3] = a.w*scale*wa.w;
    y[4] = b.x*scale*wb.x; y[5] = b.y*scale*wb.y; y[6] = b.z*scale*wb.z; y[7] = b.w*scale*wb.w;
    __align__(16) __half hv[8];
    #pragma unroll
    for (int j = 0; j < 8; j++) hv[j] = __float2half(y[j]);
    *(uint4*)(O16 + (size_t)m * DIM + tid * 8) = *(const uint4*)hv;
}

// =====================================================================
// fp16 single-pass GEMM core. CTA 128x256, warp 64x64, 8 warps,
// K-chunk 32, 8-stage cp.async. C = A@B.
// =====================================================================
#define GM_STAGES 8
#define GM_STAGE_BYTES 24576
#define GM_SMEM (GM_STAGES * GM_STAGE_BYTES)   // 196608
#define OFF_A 0
#define OFF_B 8192

__device__ __forceinline__ uint32_t swz(int r, int g) {
    return (uint32_t)(r * 64 + ((g ^ ((r >> 1) & 3)) << 4));
}

template<typename IssueF>
__device__ __forceinline__ void gemm_mainloop(
    float (&acc)[4][8][4], uint32_t sb, int nk, int wm, int wn, int lane,
    IssueF issue_stage)
{
    #pragma unroll
    for (int p = 0; p < 7; p++) { issue_stage(p, p); CP_COMMIT(); }

    for (int kc = 0; kc < nk; kc++) {
        CP_WAIT6();
        __syncthreads();
        if (kc + 7 < nk) issue_stage(kc + 7, (kc + 7) & 7);
        CP_COMMIT();

        const uint32_t st = sb + (kc & 7) * GM_STAGE_BYTES;
        #pragma unroll
        for (int h = 0; h < 2; h++) {
            uint32_t a[4][4];
            #pragma unroll
            for (int mi = 0; mi < 4; mi++) {
                const int r = wm * 64 + mi * 16 + (lane & 15);
                ldsm4(a[mi], st + OFF_A + swz(r, h * 2 + (lane >> 4)));
            }
            #pragma unroll
            for (int ng = 0; ng < 4; ng++) {
                uint32_t b[4];
                const int r = wn * 64 + ng * 16 + (lane & 15);
                ldsm4(b, st + OFF_B + swz(r, h * 2 + (lane >> 4)));
                #pragma unroll
                for (int mi = 0; mi < 4; mi++) {
                    mma_f16(acc[mi][ng * 2 + 0], a[mi], b[0], b[2]);
                    mma_f16(acc[mi][ng * 2 + 1], a[mi], b[1], b[3]);
                }
            }
        }
        __syncthreads();
    }
}

#define GEMM_ISSUE_LAMBDA(A16, B16, m0, n0, K)                                  \
    auto issue_stage = [&](int kc, int slot) {                                  \
        const uint32_t st = sb + slot * GM_STAGE_BYTES;                         \
        const int kelem = kc * 32 + lg * 8;                                     \
        _Pragma("unroll")                                                       \
        for (int i = 0; i < 2; i++) {                                           \
            const int r = lr + i * 64;                                          \
            cp_async16(st + OFF_A + swz(r, lg), A16 + (size_t)(m0 + r) * K + kelem); \
        }                                                                       \
        _Pragma("unroll")                                                       \
        for (int i = 0; i < 4; i++) {                                           \
            const int r = lr + i * 64;                                          \
            cp_async16(st + OFF_B + swz(r, lg), B16 + (size_t)(n0 + r) * K + kelem); \
        }                                                                       \
    };

// =====================================================================
// Generic GEMM: MODE 0: C=A@B+bias; 1: +extra (fp32 out);
//               2: silu(extra)*(A@B+bias) -> fp16 out C16
// =====================================================================
template<int MODE>
__global__ void __launch_bounds__(256, 1) gemm_mma(
    const __half* __restrict__ A16, const __half* __restrict__ B16,
    const float* __restrict__ bias, const float* __restrict__ extra,
    float* __restrict__ C, __half* __restrict__ C16,
    int M, int N, int K)
{
    extern __shared__ char smraw[];
    const uint32_t sb = smem_u32(smraw);
    const int tid = threadIdx.x;
    const int wid = tid >> 5;
    const int lane = tid & 31;
    const int wm = wid & 1;
    const int wn = wid >> 1;
    const int m0 = blockIdx.y * 128;
    const int n0 = blockIdx.x * 256;
    const int nk = K >> 5;
    const int lr = tid >> 2;
    const int lg = tid & 3;

    float acc[4][8][4];
    #pragma unroll
    for (int a = 0; a < 4; a++)
        #pragma unroll
        for (int b = 0; b < 8; b++)
            #pragma unroll
            for (int c = 0; c < 4; c++) acc[a][b][c] = 0.f;

    GEMM_ISSUE_LAMBDA(A16, B16, m0, n0, K)
    gemm_mainloop(acc, sb, nk, wm, wn, lane, issue_stage);

    const int mb = m0 + wm * 64;
    const int nb = n0 + wn * 64;
    #pragma unroll
    for (int mi = 0; mi < 4; mi++) {
        #pragma unroll
        for (int j = 0; j < 8; j++) {
            const int row = mb + mi * 16 + (lane >> 2);
            const int col = nb + j * 8 + (lane & 3) * 2;
            const float b0 = bias[col], b1 = bias[col + 1];
            #pragma unroll
            for (int half = 0; half < 2; half++) {
                const int rr = row + half * 8;
                float v0 = acc[mi][j][half * 2 + 0] + b0;
                float v1 = acc[mi][j][half * 2 + 1] + b1;
                if (MODE == 1) {
                    const float* ep = extra + (size_t)rr * N + col;
                    v0 += ep[0]; v1 += ep[1];
                }
                if (MODE == 2) {
                    const float* ep = extra + (size_t)rr * N + col;
                    float g0 = ep[0], g1 = ep[1];
                    v0 *= g0 / (1.f + __expf(-g0));
                    v1 *= g1 / (1.f + __expf(-g1));
                    *(__half2*)(C16 + (size_t)rr * N + col) = __floats2half2_rn(v0, v1);
                } else {
                    *(float2*)(C + (size_t)rr * N + col) = make_float2(v0, v1);
                }
            }
        }
    }
}

// =====================================================================
// Fused QKV GEMM: B = concat[wq|wk|wv] (N=6144). Epilogue: RoPE+relayout.
// Q -> single fp16; K -> fp32 + fp16; V -> fp32 + fp16.
// =====================================================================
__global__ void __launch_bounds__(256, 1) gemm_qkv(
    const __half* __restrict__ A16, const __half* __restrict__ B16,
    const float* __restrict__ bq, const float* __restrict__ bk, const float* __restrict__ bv,
    const float* __restrict__ cosb, const float* __restrict__ sinb,
    float* __restrict__ out_k, float* __restrict__ out_v,
    __half* __restrict__ Q16, __half* __restrict__ K16, __half* __restrict__ V16)
{
    extern __shared__ char smraw[];
    const uint32_t sb = smem_u32(smraw);
    const int tid = threadIdx.x;
    const int wid = tid >> 5;
    const int lane = tid & 31;
    const int wm = wid & 1;
    const int wn = wid >> 1;
    const int m0 = blockIdx.y * 128;
    const int n0 = blockIdx.x * 256;
    const int K = DIM;
    const int nk = K >> 5;
    const int lr = tid >> 2;
    const int lg = tid & 3;
    const int sec = n0 >> 11;
    const float* bias = (sec == 0) ? bq : ((sec == 1) ? bk : bv);

    float acc[4][8][4];
    #pragma unroll
    for (int a = 0; a < 4; a++)
        #pragma unroll
        for (int b = 0; b < 8; b++)
            #pragma unroll
            for (int c = 0; c < 4; c++) acc[a][b][c] = 0.f;

    GEMM_ISSUE_LAMBDA(A16, B16, m0, n0, K)
    gemm_mainloop(acc, sb, nk, wm, wn, lane, issue_stage);

    const int mb = m0 + wm * 64;
    const int nb = n0 + wn * 64;
    #pragma unroll
    for (int mi = 0; mi < 4; mi++) {
        #pragma unroll
        for (int j = 0; j < 8; j++) {
            const int row = mb + mi * 16 + (lane >> 2);
            const int col = nb + j * 8 + (lane & 3) * 2;
            const float b0 = bias[col & 2047], b1 = bias[(col & 2047) + 1];
            const int nc = col & 2047;
            const int h = nc >> 7;
            const int d = nc & 127;
            #pragma unroll
            for (int half = 0; half < 2; half++) {
                const int rr = row + half * 8;
                float v0 = acc[mi][j][half * 2 + 0] + b0;
                float v1 = acc[mi][j][half * 2 + 1] + b1;
                const int bi = rr >> 11;
                const int s = rr & 2047;
                if (sec < 2) {
                    const int i2 = d >> 1;
                    const float c = cosb[(PREV_LEN + s) * 64 + i2];
                    const float sn = sinb[(PREV_LEN + s) * 64 + i2];
                    const float r0 = v0 * c - v1 * sn;
                    const float r1 = v0 * sn + v1 * c;
                    if (sec == 0) {
                        *(__half2*)(Q16 + ((size_t)(bi * HEADS + h) * S_LEN + s) * HD + d) =
                            __floats2half2_rn(r0 * QK_SCALE, r1 * QK_SCALE);
                    } else {
                        const size_t off = ((size_t)(bi * HEADS + h) * T_LEN + PREV_LEN + s) * HD + d;
                        *(float2*)(out_k + off) = make_float2(r0, r1);
                        *(__half2*)(K16 + off) = __floats2half2_rn(r0, r1);
                    }
                } else {
                    const size_t off = ((size_t)(bi * HEADS + h) * T_LEN + PREV_LEN + s) * HD + d;
                    *(float2*)(out_v + off) = make_float2(v0, v1);
                    *(__half2*)(V16 + off) = __floats2half2_rn(v0, v1);
                }
            }
        }
    }
}

// ---------------- cache copies ----------------
__global__ __launch_bounds__(256) void copy_cache(
    const float* __restrict__ in, float* __restrict__ out,
    __half* __restrict__ H16)
{
    int idx = blockIdx.x * 256 + threadIdx.x;   // 2^20 f4
    int bh  = idx >> 15;
    int rem = idx & 32767;
    float4 v = ((const float4*)in)[idx];
    size_t off4 = (size_t)bh * (T_LEN * HD / 4) + rem;
    ((float4*)out)[off4] = v;
    __align__(8) __half hv[4];
    hv[0] = __float2half(v.x); hv[1] = __float2half(v.y);
    hv[2] = __float2half(v.z); hv[3] = __float2half(v.w);
    *(uint2*)(H16 + off4 * 4) = *(const uint2*)hv;
}

// =====================================================================
// HMMA flash attention, all fp16 single, 1-pass QK.
// smem: Q 32K | stage{0,1}: K 16K, V 16K.
// =====================================================================
#define FBM 128
#define FBN 64
#define F_OFF_Q  0
#define F_OFF_ST 32768
#define F_STAGE  32768
#define F_SMEM   (F_OFF_ST + 2 * F_STAGE)   // 98304

__device__ __forceinline__ uint32_t swz256(int r, int g) {
    return (uint32_t)((r << 8) + (((g ^ (r & 7)) & 15) << 4));
}

__global__ void __launch_bounds__(256) flash_mma(
    const __half* __restrict__ Q16, const __half* __restrict__ K16,
    const __half* __restrict__ V16, __half* __restrict__ O16)
{
    extern __shared__ char smraw[];
    const uint32_t sb = smem_u32(smraw);
    const int tid = threadIdx.x;
    const int wid = tid >> 5;
    const int lane = tid & 31;
    const int mtile = gridDim.x - 1 - blockIdx.x;
    const int bh = blockIdx.y;
    const int m0 = mtile * FBM;
    const int jend = (PREV_LEN + m0 + FBM) / FBN;
    const int mask_start = (PREV_LEN + m0) / FBN;

    {
        const size_t qo = ((size_t)bh * S_LEN + m0) * HD;
        for (int i = tid; i < 2048; i += 256) {
            int r = i >> 4, g = i & 15;
            cp_async16(sb + F_OFF_Q + swz256(r, g), Q16 + qo + (size_t)r * HD + g * 8);
        }
        CP_COMMIT();
    }

    auto issue_kv = [&](int jt, int slot) {
        const uint32_t st = sb + F_OFF_ST + slot * F_STAGE;
        const size_t ko = ((size_t)bh * T_LEN + jt * FBN) * HD;
        for (int i = tid; i < 1024; i += 256) {
            int r = i >> 4, g = i & 15;
            uint32_t sw = swz256(r, g);
            size_t go = ko + (size_t)r * HD + g * 8;
            cp_async16(st + sw, K16 + go);
            cp_async16(st + 16384 + sw, V16 + go);
        }
    };
    issue_kv(0, 0); CP_COMMIT();
    issue_kv(1, 1); CP_COMMIT();

    float of[16][4];
    #pragma unroll
    for (int i = 0; i < 16; i++)
        #pragma unroll
        for (int j = 0; j < 4; j++) of[i][j] = 0.f;
    float mrow0 = -1e30f, mrow1 = -1e30f, lrow0 = 0.f, lrow1 = 0.f;

    const int arow = wid * 16 + (lane & 15);
    const int agr  = lane >> 4;

    for (int jt = 0; jt < jend; jt++) {
        CP_WAIT1();
        __syncthreads();
        const uint32_t st = sb + F_OFF_ST + (jt & 1) * F_STAGE;
        const int t0 = jt * FBN;

        float sf[8][4];
        #pragma unroll
        for (int i = 0; i < 8; i++)
            #pragma unroll
            for (int j = 0; j < 4; j++) sf[i][j] = 0.f;

        #pragma unroll
        for (int kt = 0; kt < 8; kt++) {
            uint32_t a[4];
            ldsm4(a, sb + F_OFF_Q + swz256(arow, kt * 2 + agr));
            #pragma unroll
            for (int nb = 0; nb < 4; nb++) {
                uint32_t b[4];
                ldsm4(b, st + swz256(nb * 16 + (lane & 15), kt * 2 + agr));
                mma_f16(sf[nb * 2 + 0], a, b[0], b[2]);
                mma_f16(sf[nb * 2 + 1], a, b[1], b[3]);
            }
        }

        if (jt >= mask_start) {
            const int rb = m0 + wid * 16 + (lane >> 2);
            const int cb = t0 + (lane & 3) * 2;
            #pragma unroll
            for (int nt = 0; nt < 8; nt++) {
                const int c0 = cb + nt * 8;
                if (c0     > PREV_LEN + rb)     sf[nt][0] = -1e30f;
                if (c0 + 1 > PREV_LEN + rb)     sf[nt][1] = -1e30f;
                if (c0     > PREV_LEN + rb + 8) sf[nt][2] = -1e30f;
                if (c0 + 1 > PREV_LEN + rb + 8) sf[nt][3] = -1e30f;
            }
        }

        float mx0 = -1e30f, mx1 = -1e30f;
        #pragma unroll
        for (int nt = 0; nt < 8; nt++) {
            mx0 = fmaxf(mx0, fmaxf(sf[nt][0], sf[nt][1]));
            mx1 = fmaxf(mx1, fmaxf(sf[nt][2], sf[nt][3]));
        }
        mx0 = fmaxf(mx0, __shfl_xor_sync(0xFFFFFFFF, mx0, 1));
        mx0 = fmaxf(mx0, __shfl_xor_sync(0xFFFFFFFF, mx0, 2));
        mx1 = fmaxf(mx1, __shfl_xor_sync(0xFFFFFFFF, mx1, 1));
        mx1 = fmaxf(mx1, __shfl_xor_sync(0xFFFFFFFF, mx1, 2));
        const float nm0 = fmaxf(mrow0, mx0);
        const float nm1 = fmaxf(mrow1, mx1);
        const float al0 = __expf(mrow0 - nm0);
        const float al1 = __expf(mrow1 - nm1);
        mrow0 = nm0; mrow1 = nm1;

        float rs0 = 0.f, rs1 = 0.f;
        #pragma unroll
        for (int nt = 0; nt < 8; nt++) {
            sf[nt][0] = __expf(sf[nt][0] - nm0);
            sf[nt][1] = __expf(sf[nt][1] - nm0);
            sf[nt][2] = __expf(sf[nt][2] - nm1);
            sf[nt][3] = __expf(sf[nt][3] - nm1);
            rs0 += sf[nt][0] + sf[nt][1];
            rs1 += sf[nt][2] + sf[nt][3];
        }
        rs0 += __shfl_xor_sync(0xFFFFFFFF, rs0, 1);
        rs0 += __shfl_xor_sync(0xFFFFFFFF, rs0, 2);
        rs1 += __shfl_xor_sync(0xFFFFFFFF, rs1, 1);
        rs1 += __shfl_xor_sync(0xFFFFFFFF, rs1, 2);
        lrow0 = lrow0 * al0 + rs0;
        lrow1 = lrow1 * al1 + rs1;

        #pragma unroll
        for (int nt = 0; nt < 16; nt++) {
            of[nt][0] *= al0; of[nt][1] *= al0;
            of[nt][2] *= al1; of[nt][3] *= al1;
        }

        #pragma unroll
        for (int kt = 0; kt < 4; kt++) {
            uint32_t a[4];
            a[0] = pack_f16(sf[2 * kt][0],     sf[2 * kt][1]);
            a[1] = pack_f16(sf[2 * kt][2],     sf[2 * kt][3]);
            a[2] = pack_f16(sf[2 * kt + 1][0], sf[2 * kt + 1][1]);
            a[3] = pack_f16(sf[2 * kt + 1][2], sf[2 * kt + 1][3]);
            const int vrow = kt * 16 + ((lane >> 3) & 1) * 8 + (lane & 7);
            #pragma unroll
            for (int nb = 0; nb < 8; nb++) {
                uint32_t b[4];
                ldsm4t(b, st + 16384 + swz256(vrow, nb * 2 + ((lane >> 4) & 1)));
                mma_f16(of[nb * 2 + 0], a, b[0], b[1]);
                mma_f16(of[nb * 2 + 1], a, b[2], b[3]);
            }
        }

        __syncthreads();
        if (jt + 2 < jend) issue_kv(jt + 2, jt & 1);
        CP_COMMIT();
    }

    const float inv0 = 1.f / lrow0;
    const float inv1 = 1.f / lrow1;
    const int b = bh >> 4, h = bh & 15;
    const int r0 = m0 + wid * 16 + (lane >> 2);
    #pragma unroll
    for (int nt = 0; nt < 16; nt++) {
        const int gc = h * HD + nt * 8 + (lane & 3) * 2;
        *(__half2*)(O16 + (size_t)(b * S_LEN + r0) * DIM + gc) =
            __floats2half2_rn(of[nt][0] * inv0, of[nt][1] * inv0);
        *(__half2*)(O16 + (size_t)(b * S_LEN + r0 + 8) * DIM + gc) =
            __floats2half2_rn(of[nt][2] * inv1, of[nt][3] * inv1);
    }
}

// ---------------- launch ----------------
extern "C" void kernel_launch(void* const* d_in, const int* in_sizes, int n_in,
                              void* d_out, int out_size)
{
    const float* x          = (const float*)d_in[0];
    const float* k_cache    = (const float*)d_in[1];
    const float* v_cache    = (const float*)d_in[2];
    const float* attn_norm_w= (const float*)d_in[3];
    const float* ffn_norm_w = (const float*)d_in[4];
    const float* wq = (const float*)d_in[5];
    const float* bq = (const float*)d_in[6];
    const float* wk = (const float*)d_in[7];
    const float* bk = (const float*)d_in[8];
    const float* wv = (const float*)d_in[9];
    const float* bv = (const float*)d_in[10];
    const float* wo = (const float*)d_in[11];
    const float* bo = (const float*)d_in[12];
    const float* w_gate = (const float*)d_in[13];
    const float* b_gate = (const float*)d_in[14];
    const float* w_val  = (const float*)d_in[15];
    const float* b_val  = (const float*)d_in[16];
    const float* w_proj = (const float*)d_in[17];
    const float* b_proj = (const float*)d_in[18];
    const float* fcos   = (const float*)d_in[19];
    const float* fsin   = (const float*)d_in[20];

    float* out_x = (float*)d_out;
    float* out_k = out_x + OUT_X_ELEMS;
    float* out_v = out_k + OUT_KV_ELEMS;

    float *p_x1, *p_g;
    __half *p_hA16, *p_h216, *p_o16, *p_gt16;
    __half *p_q16, *p_k16, *p_v16;
    __half *p_wqkv, *p_wo, *p_wg, *p_wv2, *p_wp;

    cudaGetSymbolAddress((void**)&p_x1, g_x1);
    cudaGetSymbolAddress((void**)&p_g,  g_g);
    cudaGetSymbolAddress((void**)&p_hA16, g_hA16);
    cudaGetSymbolAddress((void**)&p_h216, g_h216);
    cudaGetSymbolAddress((void**)&p_o16,  g_o16);
    cudaGetSymbolAddress((void**)&p_gt16, g_gt16);
    cudaGetSymbolAddress((void**)&p_q16,  g_q16);
    cudaGetSymbolAddress((void**)&p_k16,  g_k16);
    cudaGetSymbolAddress((void**)&p_v16,  g_v16);
    cudaGetSymbolAddress((void**)&p_wqkv, g_wqkv);
    cudaGetSymbolAddress((void**)&p_wo,   g_wo);
    cudaGetSymbolAddress((void**)&p_wg,   g_wg);
    cudaGetSymbolAddress((void**)&p_wv2,  g_wv2);
    cudaGetSymbolAddress((void**)&p_wp,   g_wp);

    cudaFuncSetAttribute(gemm_mma<0>, cudaFuncAttributeMaxDynamicSharedMemorySize, GM_SMEM);
    cudaFuncSetAttribute(gemm_mma<1>, cudaFuncAttributeMaxDynamicSharedMemorySize, GM_SMEM);
    cudaFuncSetAttribute(gemm_mma<2>, cudaFuncAttributeMaxDynamicSharedMemorySize, GM_SMEM);
    cudaFuncSetAttribute(gemm_qkv,   cudaFuncAttributeMaxDynamicSharedMemorySize, GM_SMEM);
    cudaFuncSetAttribute(flash_mma, cudaFuncAttributeMaxDynamicSharedMemorySize, F_SMEM);

    // ---- weight conversion + transpose (grid: K/32, N/128) ----
    weight_conv_t<<<dim3(64, 16), 256>>>(wq, p_wqkv,                 DIM, DIM);
    weight_conv_t<<<dim3(64, 16), 256>>>(wk, p_wqkv + DIM * DIM,     DIM, DIM);
    weight_conv_t<<<dim3(64, 16), 256>>>(wv, p_wqkv + 2 * DIM * DIM, DIM, DIM);
    weight_conv_t<<<dim3(64, 16), 256>>>(wo, p_wo, DIM, DIM);
    weight_conv_t<<<dim3(64, 64), 256>>>(w_gate, p_wg,  FF_DIM, DIM);
    weight_conv_t<<<dim3(64, 64), 256>>>(w_val,  p_wv2, FF_DIM, DIM);
    weight_conv_t<<<dim3(256, 16), 256>>>(w_proj, p_wp, DIM, FF_DIM);

    // ---- attention block ----
    rmsnorm_h<<<ROWS, 256>>>(x, attn_norm_w, p_hA16);
    gemm_qkv<<<dim3(24, 32), 256, GM_SMEM>>>(
        p_hA16, p_wqkv, bq, bk, bv, fcos, fsin,
        out_k, out_v, p_q16, p_k16, p_v16);

    copy_cache<<<4096, 256>>>(k_cache, out_k, p_k16);
    copy_cache<<<4096, 256>>>(v_cache, out_v, p_v16);

    flash_mma<<<dim3(S_LEN / FBM, BATCH * HEADS), 256, F_SMEM>>>(
        p_q16, p_k16, p_v16, p_o16);

    gemm_mma<1><<<dim3(8, 32), 256, GM_SMEM>>>(
        p_o16, p_wo, bo, x, p_x1, nullptr, ROWS, DIM, DIM);

    // ---- ffn block ----
    rmsnorm_h<<<ROWS, 256>>>(p_x1, ffn_norm_w, p_h216);
    gemm_mma<0><<<dim3(32, 32), 256, GM_SMEM>>>(
        p_h216, p_wg, b_gate, nullptr, p_g, nullptr, ROWS, FF_DIM, DIM);
    gemm_mma<2><<<dim3(32, 32), 256, GM_SMEM>>>(
        p_h216, p_wv2, b_val, p_g, nullptr, p_gt16, ROWS, FF_DIM, DIM);
    gemm_mma<1><<<dim3(8, 32), 256, GM_SMEM>>>(
        p_gt16, p_wp, b_proj, p_x1, out_x, nullptr, ROWS, DIM, FF_DIM);
}

// round 10
// speedup vs baseline: 2.5565x; 1.0824x over previous
#include <cuda_runtime.h>
#include <cuda_bf16.h>
#include <cuda_fp16.h>
#include <cstdint>

// ---------------- problem constants ----------------
#define BATCH 2
#define S_LEN 2048
#define PREV_LEN 1024
#define T_LEN 3072
#define DIM 2048
#define HEADS 16
#define HD 128
#define FF_DIM 8192
#define ROWS (BATCH * S_LEN)  // 4096
#define QK_SCALE 0.08838834764831845f

#define OUT_X_ELEMS  (BATCH * S_LEN * DIM)
#define OUT_KV_ELEMS (BATCH * HEADS * T_LEN * HD)

// ================= PTX helpers (portable sm_80+) ====
__device__ __forceinline__ uint32_t smem_u32(const void* p) {
    uint32_t a;
    asm("{ .reg .u64 t; cvta.to.shared.u64 t, %1; cvt.u32.u64 %0, t; }" : "=r"(a) : "l"(p));
    return a;
}
__device__ __forceinline__ void cp_async16(uint32_t smem, const void* g) {
    asm volatile("cp.async.cg.shared.global [%0], [%1], 16;" :: "r"(smem), "l"(g) : "memory");
}
#define CP_COMMIT() asm volatile("cp.async.commit_group;" ::: "memory")
#define CP_WAIT6()  asm volatile("cp.async.wait_group 6;" ::: "memory")
#define CP_WAIT1()  asm volatile("cp.async.wait_group 1;" ::: "memory")

__device__ __forceinline__ void ldsm4(uint32_t* r, uint32_t addr) {
    asm volatile("ldmatrix.sync.aligned.m8n8.x4.shared.b16 {%0,%1,%2,%3}, [%4];"
        : "=r"(r[0]), "=r"(r[1]), "=r"(r[2]), "=r"(r[3]) : "r"(addr));
}
__device__ __forceinline__ void ldsm4t(uint32_t* r, uint32_t addr) {
    asm volatile("ldmatrix.sync.aligned.m8n8.x4.trans.shared.b16 {%0,%1,%2,%3}, [%4];"
        : "=r"(r[0]), "=r"(r[1]), "=r"(r[2]), "=r"(r[3]) : "r"(addr));
}
__device__ __forceinline__ void mma_f16(float* c, const uint32_t* a, uint32_t b0, uint32_t b1) {
    asm volatile(
        "mma.sync.aligned.m16n8k16.row.col.f32.f16.f16.f32 "
        "{%0,%1,%2,%3}, {%4,%5,%6,%7}, {%8,%9}, {%0,%1,%2,%3};"
        : "+f"(c[0]), "+f"(c[1]), "+f"(c[2]), "+f"(c[3])
        : "r"(a[0]), "r"(a[1]), "r"(a[2]), "r"(a[3]), "r"(b0), "r"(b1));
}
__device__ __forceinline__ uint32_t pack_f16(float a, float b) {
    __half2 t = __floats2half2_rn(a, b);
    return *(uint32_t*)&t;
}

// ---------------- scratch (device globals) --------
__device__ float g_x1 [ROWS * DIM];
// fp16 single activations (GEMM A operands)
__device__ __half g_hA16 [ROWS * DIM];
__device__ __half g_h216 [ROWS * DIM];
__device__ __half g_o16  [ROWS * DIM];
__device__ __half g_gt16 [ROWS * FF_DIM];
// fp16 attention operands (b,h,s/t,d)
__device__ __half g_q16 [ROWS * DIM];
__device__ __half g_k16 [OUT_KV_ELEMS];
__device__ __half g_v16 [OUT_KV_ELEMS];
// fp16 transposed weights [N][K]
__device__ __half g_wqkv[3 * DIM * DIM];
__device__ __half g_wo  [DIM * DIM];
__device__ __half g_wg  [DIM * FF_DIM];
__device__ __half g_wv2 [DIM * FF_DIM];
__device__ __half g_wp  [FF_DIM * DIM];

// =====================================================================
// Weight converter + transpose body: W[K][N] fp32 -> Wt[N][K] fp16.
// block = (256), tile 32(k) x 128(n).
// =====================================================================
__device__ __forceinline__ void wconv_body(
    const float* __restrict__ W, __half* __restrict__ T16, int N, int K)
{
    __shared__ float tile[32][133];
    const int k0 = blockIdx.x * 32, n0 = blockIdx.y * 128;
    const int tid = threadIdx.x;
    {
        const int kr = tid >> 3;
        const int nq = (tid & 7) * 16;
        const float* src = W + (size_t)(k0 + kr) * N + n0 + nq;
        #pragma unroll
        for (int u = 0; u < 4; u++) {
            float4 v = *(const float4*)(src + u * 4);
            tile[kr][nq + u * 4 + 0] = v.x;
            tile[kr][nq + u * 4 + 1] = v.y;
            tile[kr][nq + u * 4 + 2] = v.z;
            tile[kr][nq + u * 4 + 3] = v.w;
        }
    }
    __syncthreads();
    const int n = tid >> 1;
    const int q = tid & 1;
    __align__(16) __half hv[16];
    #pragma unroll
    for (int u = 0; u < 16; u++)
        hv[u] = __float2half(tile[q * 16 + u][n]);
    const size_t off = (size_t)(n0 + n) * K + k0 + q * 16;
    *(uint4*)(T16 + off)     = *(const uint4*)(hv);
    *(uint4*)(T16 + off + 8) = *(const uint4*)(hv + 8);
}

__global__ __launch_bounds__(256) void weight_conv1(
    const float* __restrict__ W, __half* __restrict__ T, int N, int K)
{
    wconv_body(W, T, N, K);
}
__global__ __launch_bounds__(256) void weight_conv2(
    const float* __restrict__ W0, const float* __restrict__ W1,
    __half* __restrict__ T0, __half* __restrict__ T1, int N, int K)
{
    const float* W = blockIdx.z ? W1 : W0;
    __half* T = blockIdx.z ? T1 : T0;
    wconv_body(W, T, N, K);
}
__global__ __launch_bounds__(256) void weight_conv4(
    const float* __restrict__ W0, const float* __restrict__ W1,
    const float* __restrict__ W2, const float* __restrict__ W3,
    __half* __restrict__ T0, __half* __restrict__ T1,
    __half* __restrict__ T2, __half* __restrict__ T3, int N, int K)
{
    const int z = blockIdx.z;
    const float* W = (z == 0) ? W0 : (z == 1) ? W1 : (z == 2) ? W2 : W3;
    __half* T = (z == 0) ? T0 : (z == 1) ? T1 : (z == 2) ? T2 : T3;
    wconv_body(W, T, N, K);
}

// =====================================================================
// rmsnorm -> single fp16 row-major
// =====================================================================
__global__ __launch_bounds__(256) void rmsnorm_h(
    const float* __restrict__ x, const float* __restrict__ w,
    __half* __restrict__ O16)
{
    __shared__ float red[256];
    const int tid = threadIdx.x;
    const int m = blockIdx.x;
    const float* xp = x + (size_t)m * DIM + tid * 8;
    float4 a = *(const float4*)xp;
    float4 b = *(const float4*)(xp + 4);
    float s = a.x*a.x + a.y*a.y + a.z*a.z + a.w*a.w
            + b.x*b.x + b.y*b.y + b.z*b.z + b.w*b.w;
    red[tid] = s;
    __syncthreads();
    #pragma unroll
    for (int off = 128; off > 0; off >>= 1) {
        if (tid < off) red[tid] += red[tid + off];
        __syncthreads();
    }
    float scale = rsqrtf(red[0] * (1.0f / DIM) + 1e-6f);
    const float* wp = w + tid * 8;
    float4 wa = *(const float4*)wp;
    float4 wb = *(const float4*)(wp + 4);
    float y[8];
    y[0] = a.x*scale*wa.x; y[1] = a.y*scale*wa.y; y[2] = a.z*scale*wa.z; y[3] = a.w*scale*wa.w;
    y[4] = b.x*scale*wb.x; y[5] = b.y*scale*wb.y; y[6] = b.z*scale*wb.z; y[7] = b.w*scale*wb.w;
    __align__(16) __half hv[8];
    #pragma unroll
    for (int j = 0; j < 8; j++) hv[j] = __float2half(y[j]);
    *(uint4*)(O16 + (size_t)m * DIM + tid * 8) = *(const uint4*)hv;
}

// =====================================================================
// fp16 single-pass GEMM core. CTA 128x256, warp 64x64, 8 warps,
// K-chunk 32, 8-stage cp.async, single barrier per chunk.
// =====================================================================
#define GM_STAGES 8
#define GM_STAGE_BYTES 24576
#define GM_SMEM (GM_STAGES * GM_STAGE_BYTES)   // 196608
#define OFF_A 0
#define OFF_B 8192

__device__ __forceinline__ uint32_t swz(int r, int g) {
    return (uint32_t)(r * 64 + ((g ^ ((r >> 1) & 3)) << 4));
}

template<typename IssueF>
__device__ __forceinline__ void gemm_mainloop(
    float (&acc)[4][8][4], uint32_t sb, int nk, int wm, int wn, int lane,
    IssueF issue_stage)
{
    #pragma unroll
    for (int p = 0; p < 7; p++) { issue_stage(p, p); CP_COMMIT(); }

    for (int kc = 0; kc < nk; kc++) {
        CP_WAIT6();
        __syncthreads();
        if (kc + 7 < nk) issue_stage(kc + 7, (kc + 7) & 7);
        CP_COMMIT();

        const uint32_t st = sb + (kc & 7) * GM_STAGE_BYTES;
        #pragma unroll
        for (int h = 0; h < 2; h++) {
            uint32_t a[4][4];
            #pragma unroll
            for (int mi = 0; mi < 4; mi++) {
                const int r = wm * 64 + mi * 16 + (lane & 15);
                ldsm4(a[mi], st + OFF_A + swz(r, h * 2 + (lane >> 4)));
            }
            #pragma unroll
            for (int ng = 0; ng < 4; ng++) {
                uint32_t b[4];
                const int r = wn * 64 + ng * 16 + (lane & 15);
                ldsm4(b, st + OFF_B + swz(r, h * 2 + (lane >> 4)));
                #pragma unroll
                for (int mi = 0; mi < 4; mi++) {
                    mma_f16(acc[mi][ng * 2 + 0], a[mi], b[0], b[2]);
                    mma_f16(acc[mi][ng * 2 + 1], a[mi], b[1], b[3]);
                }
            }
        }
        // no trailing sync: next iteration's issue targets the slot whose
        // reads completed before this iteration's top barrier.
    }
}

#define GEMM_ISSUE_LAMBDA(A16, B16, m0, n0, K)                                  \
    auto issue_stage = [&](int kc, int slot) {                                  \
        const uint32_t st = sb + slot * GM_STAGE_BYTES;                         \
        const int kelem = kc * 32 + lg * 8;                                     \
        _Pragma("unroll")                                                       \
        for (int i = 0; i < 2; i++) {                                           \
            const int r = lr + i * 64;                                          \
            cp_async16(st + OFF_A + swz(r, lg), A16 + (size_t)(m0 + r) * K + kelem); \
        }                                                                       \
        _Pragma("unroll")                                                       \
        for (int i = 0; i < 4; i++) {                                           \
            const int r = lr + i * 64;                                          \
            cp_async16(st + OFF_B + swz(r, lg), B16 + (size_t)(n0 + r) * K + kelem); \
        }                                                                       \
    };

// =====================================================================
// Generic GEMM (MODE 1 only used): C = A@B + bias + extra (fp32 out)
// =====================================================================
template<int MODE>
__global__ void __launch_bounds__(256, 1) gemm_mma(
    const __half* __restrict__ A16, const __half* __restrict__ B16,
    const float* __restrict__ bias, const float* __restrict__ extra,
    float* __restrict__ C, __half* __restrict__ C16,
    int M, int N, int K)
{
    extern __shared__ char smraw[];
    const uint32_t sb = smem_u32(smraw);
    const int tid = threadIdx.x;
    const int wid = tid >> 5;
    const int lane = tid & 31;
    const int wm = wid & 1;
    const int wn = wid >> 1;
    const int m0 = blockIdx.y * 128;
    const int n0 = blockIdx.x * 256;
    const int nk = K >> 5;
    const int lr = tid >> 2;
    const int lg = tid & 3;

    float acc[4][8][4];
    #pragma unroll
    for (int a = 0; a < 4; a++)
        #pragma unroll
        for (int b = 0; b < 8; b++)
            #pragma unroll
            for (int c = 0; c < 4; c++) acc[a][b][c] = 0.f;

    GEMM_ISSUE_LAMBDA(A16, B16, m0, n0, K)
    gemm_mainloop(acc, sb, nk, wm, wn, lane, issue_stage);

    const int mb = m0 + wm * 64;
    const int nb = n0 + wn * 64;
    #pragma unroll
    for (int mi = 0; mi < 4; mi++) {
        #pragma unroll
        for (int j = 0; j < 8; j++) {
            const int row = mb + mi * 16 + (lane >> 2);
            const int col = nb + j * 8 + (lane & 3) * 2;
            const float b0 = bias[col], b1 = bias[col + 1];
            #pragma unroll
            for (int half = 0; half < 2; half++) {
                const int rr = row + half * 8;
                float v0 = acc[mi][j][half * 2 + 0] + b0;
                float v1 = acc[mi][j][half * 2 + 1] + b1;
                if (MODE == 1) {
                    const float* ep = extra + (size_t)rr * N + col;
                    v0 += ep[0]; v1 += ep[1];
                }
                *(float2*)(C + (size_t)rr * N + col) = make_float2(v0, v1);
            }
        }
    }
}

// =====================================================================
// Fused QKV GEMM: B = concat[wq|wk|wv] (N=6144). Epilogue: RoPE+relayout.
// =====================================================================
__global__ void __launch_bounds__(256, 1) gemm_qkv(
    const __half* __restrict__ A16, const __half* __restrict__ B16,
    const float* __restrict__ bq, const float* __restrict__ bk, const float* __restrict__ bv,
    const float* __restrict__ cosb, const float* __restrict__ sinb,
    float* __restrict__ out_k, float* __restrict__ out_v,
    __half* __restrict__ Q16, __half* __restrict__ K16, __half* __restrict__ V16)
{
    extern __shared__ char smraw[];
    const uint32_t sb = smem_u32(smraw);
    const int tid = threadIdx.x;
    const int wid = tid >> 5;
    const int lane = tid & 31;
    const int wm = wid & 1;
    const int wn = wid >> 1;
    const int m0 = blockIdx.y * 128;
    const int n0 = blockIdx.x * 256;
    const int K = DIM;
    const int nk = K >> 5;
    const int lr = tid >> 2;
    const int lg = tid & 3;
    const int sec = n0 >> 11;
    const float* bias = (sec == 0) ? bq : ((sec == 1) ? bk : bv);

    float acc[4][8][4];
    #pragma unroll
    for (int a = 0; a < 4; a++)
        #pragma unroll
        for (int b = 0; b < 8; b++)
            #pragma unroll
            for (int c = 0; c < 4; c++) acc[a][b][c] = 0.f;

    GEMM_ISSUE_LAMBDA(A16, B16, m0, n0, K)
    gemm_mainloop(acc, sb, nk, wm, wn, lane, issue_stage);

    const int mb = m0 + wm * 64;
    const int nb = n0 + wn * 64;
    #pragma unroll
    for (int mi = 0; mi < 4; mi++) {
        #pragma unroll
        for (int j = 0; j < 8; j++) {
            const int row = mb + mi * 16 + (lane >> 2);
            const int col = nb + j * 8 + (lane & 3) * 2;
            const float b0 = bias[col & 2047], b1 = bias[(col & 2047) + 1];
            const int nc = col & 2047;
            const int h = nc >> 7;
            const int d = nc & 127;
            #pragma unroll
            for (int half = 0; half < 2; half++) {
                const int rr = row + half * 8;
                float v0 = acc[mi][j][half * 2 + 0] + b0;
                float v1 = acc[mi][j][half * 2 + 1] + b1;
                const int bi = rr >> 11;
                const int s = rr & 2047;
                if (sec < 2) {
                    const int i2 = d >> 1;
                    const float c = cosb[(PREV_LEN + s) * 64 + i2];
                    const float sn = sinb[(PREV_LEN + s) * 64 + i2];
                    const float r0 = v0 * c - v1 * sn;
                    const float r1 = v0 * sn + v1 * c;
                    if (sec == 0) {
                        *(__half2*)(Q16 + ((size_t)(bi * HEADS + h) * S_LEN + s) * HD + d) =
                            __floats2half2_rn(r0 * QK_SCALE, r1 * QK_SCALE);
                    } else {
                        const size_t off = ((size_t)(bi * HEADS + h) * T_LEN + PREV_LEN + s) * HD + d;
                        *(float2*)(out_k + off) = make_float2(r0, r1);
                        *(__half2*)(K16 + off) = __floats2half2_rn(r0, r1);
                    }
                } else {
                    const size_t off = ((size_t)(bi * HEADS + h) * T_LEN + PREV_LEN + s) * HD + d;
                    *(float2*)(out_v + off) = make_float2(v0, v1);
                    *(__half2*)(V16 + off) = __floats2half2_rn(v0, v1);
                }
            }
        }
    }
}

// =====================================================================
// Fused FFN gate+val GEMM: CTA tile 128(M)x128(N) of BOTH wg and wv2.
// C16 = silu(A@Bg + bg) * (A@Bv + bv), fp16 out.
// stage: A 8K | Bg 8K | Bv 8K = 24KB, 8 stages.
// =====================================================================
#define FO_A  0
#define FO_BG 8192
#define FO_BV 16384

__global__ void __launch_bounds__(256, 1) gemm_ffn(
    const __half* __restrict__ A16,
    const __half* __restrict__ Bg, const __half* __restrict__ Bv,
    const float* __restrict__ bias_g, const float* __restrict__ bias_v,
    __half* __restrict__ C16)
{
    extern __shared__ char smraw[];
    const uint32_t sb = smem_u32(smraw);
    const int tid = threadIdx.x;
    const int wid = tid >> 5;
    const int lane = tid & 31;
    const int wm = wid & 1;        // 2 x 64 rows
    const int wn = wid >> 1;       // 4 x 32 cols
    const int m0 = blockIdx.y * 128;
    const int n0 = blockIdx.x * 128;
    const int K = DIM;
    const int nk = K >> 5;         // 64
    const int lr = tid >> 2;
    const int lg = tid & 3;

    float ag[4][4][4], av[4][4][4];
    #pragma unroll
    for (int a = 0; a < 4; a++)
        #pragma unroll
        for (int b = 0; b < 4; b++)
            #pragma unroll
            for (int c = 0; c < 4; c++) { ag[a][b][c] = 0.f; av[a][b][c] = 0.f; }

    auto issue_stage = [&](int kc, int slot) {
        const uint32_t st = sb + slot * GM_STAGE_BYTES;
        const int kelem = kc * 32 + lg * 8;
        #pragma unroll
        for (int i = 0; i < 2; i++) {
            const int r = lr + i * 64;
            const uint32_t sw = swz(r, lg);
            cp_async16(st + FO_A  + sw, A16 + (size_t)(m0 + r) * K + kelem);
            cp_async16(st + FO_BG + sw, Bg  + (size_t)(n0 + r) * K + kelem);
            cp_async16(st + FO_BV + sw, Bv  + (size_t)(n0 + r) * K + kelem);
        }
    };

    #pragma unroll
    for (int p = 0; p < 7; p++) { issue_stage(p, p); CP_COMMIT(); }

    for (int kc = 0; kc < nk; kc++) {
        CP_WAIT6();
        __syncthreads();
        if (kc + 7 < nk) issue_stage(kc + 7, (kc + 7) & 7);
        CP_COMMIT();

        const uint32_t st = sb + (kc & 7) * GM_STAGE_BYTES;
        #pragma unroll
        for (int h = 0; h < 2; h++) {
            uint32_t a[4][4];
            #pragma unroll
            for (int mi = 0; mi < 4; mi++) {
                const int r = wm * 64 + mi * 16 + (lane & 15);
                ldsm4(a[mi], st + FO_A + swz(r, h * 2 + (lane >> 4)));
            }
            #pragma unroll
            for (int ng = 0; ng < 2; ng++) {
                const int r = wn * 32 + ng * 16 + (lane & 15);
                const uint32_t sw = swz(r, h * 2 + (lane >> 4));
                uint32_t bg[4], bv[4];
                ldsm4(bg, st + FO_BG + sw);
                ldsm4(bv, st + FO_BV + sw);
                #pragma unroll
                for (int mi = 0; mi < 4; mi++) {
                    mma_f16(ag[mi][ng * 2 + 0], a[mi], bg[0], bg[2]);
                    mma_f16(ag[mi][ng * 2 + 1], a[mi], bg[1], bg[3]);
                    mma_f16(av[mi][ng * 2 + 0], a[mi], bv[0], bv[2]);
                    mma_f16(av[mi][ng * 2 + 1], a[mi], bv[1], bv[3]);
                }
            }
        }
    }

    const int mb = m0 + wm * 64;
    const int nb = n0 + wn * 32;
    #pragma unroll
    for (int mi = 0; mi < 4; mi++) {
        #pragma unroll
        for (int j = 0; j < 4; j++) {
            const int row = mb + mi * 16 + (lane >> 2);
            const int col = nb + j * 8 + (lane & 3) * 2;
            const float bg0 = bias_g[col], bg1 = bias_g[col + 1];
            const float bv0 = bias_v[col], bv1 = bias_v[col + 1];
            #pragma unroll
            for (int half = 0; half < 2; half++) {
                const int rr = row + half * 8;
                float gv0 = ag[mi][j][half * 2 + 0] + bg0;
                float gv1 = ag[mi][j][half * 2 + 1] + bg1;
                float vv0 = av[mi][j][half * 2 + 0] + bv0;
                float vv1 = av[mi][j][half * 2 + 1] + bv1;
                float o0 = gv0 / (1.f + __expf(-gv0)) * vv0;
                float o1 = gv1 / (1.f + __expf(-gv1)) * vv1;
                *(__half2*)(C16 + (size_t)rr * FF_DIM + col) = __floats2half2_rn(o0, o1);
            }
        }
    }
}

// ---------------- cache copies ----------------
__global__ __launch_bounds__(256) void copy_cache(
    const float* __restrict__ in, float* __restrict__ out,
    __half* __restrict__ H16)
{
    int idx = blockIdx.x * 256 + threadIdx.x;   // 2^20 f4
    int bh  = idx >> 15;
    int rem = idx & 32767;
    float4 v = ((const float4*)in)[idx];
    size_t off4 = (size_t)bh * (T_LEN * HD / 4) + rem;
    ((float4*)out)[off4] = v;
    __align__(8) __half hv[4];
    hv[0] = __float2half(v.x); hv[1] = __float2half(v.y);
    hv[2] = __float2half(v.z); hv[3] = __float2half(v.w);
    *(uint2*)(H16 + off4 * 4) = *(const uint2*)hv;
}

// =====================================================================
// HMMA flash attention, fp16 1-pass QK, 3-stage KV pipeline,
// single barrier per tile.
// smem: Q 32K | stage{0,1,2}: K 16K, V 16K.
// =====================================================================
#define FBM 128
#define FBN 64
#define F_OFF_Q  0
#define F_OFF_ST 32768
#define F_STAGE  32768
#define F_SMEM   (F_OFF_ST + 3 * F_STAGE)   // 131072

__device__ __forceinline__ uint32_t swz256(int r, int g) {
    return (uint32_t)((r << 8) + (((g ^ (r & 7)) & 15) << 4));
}

__global__ void __launch_bounds__(256) flash_mma(
    const __half* __restrict__ Q16, const __half* __restrict__ K16,
    const __half* __restrict__ V16, __half* __restrict__ O16)
{
    extern __shared__ char smraw[];
    const uint32_t sb = smem_u32(smraw);
    const int tid = threadIdx.x;
    const int wid = tid >> 5;
    const int lane = tid & 31;
    const int mtile = gridDim.x - 1 - blockIdx.x;
    const int bh = blockIdx.y;
    const int m0 = mtile * FBM;
    const int jend = (PREV_LEN + m0 + FBM) / FBN;
    const int mask_start = (PREV_LEN + m0) / FBN;

    {
        const size_t qo = ((size_t)bh * S_LEN + m0) * HD;
        for (int i = tid; i < 2048; i += 256) {
            int r = i >> 4, g = i & 15;
            cp_async16(sb + F_OFF_Q + swz256(r, g), Q16 + qo + (size_t)r * HD + g * 8);
        }
        CP_COMMIT();
    }

    auto issue_kv = [&](int jt, int slot) {
        const uint32_t st = sb + F_OFF_ST + slot * F_STAGE;
        const size_t ko = ((size_t)bh * T_LEN + jt * FBN) * HD;
        for (int i = tid; i < 1024; i += 256) {
            int r = i >> 4, g = i & 15;
            uint32_t sw = swz256(r, g);
            size_t go = ko + (size_t)r * HD + g * 8;
            cp_async16(st + sw, K16 + go);
            cp_async16(st + 16384 + sw, V16 + go);
        }
    };
    issue_kv(0, 0); CP_COMMIT();
    issue_kv(1, 1); CP_COMMIT();

    float of[16][4];
    #pragma unroll
    for (int i = 0; i < 16; i++)
        #pragma unroll
        for (int j = 0; j < 4; j++) of[i][j] = 0.f;
    float mrow0 = -1e30f, mrow1 = -1e30f, lrow0 = 0.f, lrow1 = 0.f;

    const int arow = wid * 16 + (lane & 15);
    const int agr  = lane >> 4;

    int slot = 0;        // jt % 3
    int slot2 = 2;       // (jt+2) % 3
    for (int jt = 0; jt < jend; jt++) {
        CP_WAIT1();
        __syncthreads();
        if (jt + 2 < jend) issue_kv(jt + 2, slot2);
        CP_COMMIT();

        const uint32_t st = sb + F_OFF_ST + slot * F_STAGE;
        const int t0 = jt * FBN;

        float sf[8][4];
        #pragma unroll
        for (int i = 0; i < 8; i++)
            #pragma unroll
            for (int j = 0; j < 4; j++) sf[i][j] = 0.f;

        #pragma unroll
        for (int kt = 0; kt < 8; kt++) {
            uint32_t a[4];
            ldsm4(a, sb + F_OFF_Q + swz256(arow, kt * 2 + agr));
            #pragma unroll
            for (int nb = 0; nb < 4; nb++) {
                uint32_t b[4];
                ldsm4(b, st + swz256(nb * 16 + (lane & 15), kt * 2 + agr));
                mma_f16(sf[nb * 2 + 0], a, b[0], b[2]);
                mma_f16(sf[nb * 2 + 1], a, b[1], b[3]);
            }
        }

        if (jt >= mask_start) {
            const int rb = m0 + wid * 16 + (lane >> 2);
            const int cb = t0 + (lane & 3) * 2;
            #pragma unroll
            for (int nt = 0; nt < 8; nt++) {
                const int c0 = cb + nt * 8;
                if (c0     > PREV_LEN + rb)     sf[nt][0] = -1e30f;
                if (c0 + 1 > PREV_LEN + rb)     sf[nt][1] = -1e30f;
                if (c0     > PREV_LEN + rb + 8) sf[nt][2] = -1e30f;
                if (c0 + 1 > PREV_LEN + rb + 8) sf[nt][3] = -1e30f;
            }
        }

        float mx0 = -1e30f, mx1 = -1e30f;
        #pragma unroll
        for (int nt = 0; nt < 8; nt++) {
            mx0 = fmaxf(mx0, fmaxf(sf[nt][0], sf[nt][1]));
            mx1 = fmaxf(mx1, fmaxf(sf[nt][2], sf[nt][3]));
        }
        mx0 = fmaxf(mx0, __shfl_xor_sync(0xFFFFFFFF, mx0, 1));
        mx0 = fmaxf(mx0, __shfl_xor_sync(0xFFFFFFFF, mx0, 2));
        mx1 = fmaxf(mx1, __shfl_xor_sync(0xFFFFFFFF, mx1, 1));
        mx1 = fmaxf(mx1, __shfl_xor_sync(0xFFFFFFFF, mx1, 2));
        const float nm0 = fmaxf(mrow0, mx0);
        const float nm1 = fmaxf(mrow1, mx1);
        const float al0 = __expf(mrow0 - nm0);
        const float al1 = __expf(mrow1 - nm1);
        mrow0 = nm0; mrow1 = nm1;

        float rs0 = 0.f, rs1 = 0.f;
        #pragma unroll
        for (int nt = 0; nt < 8; nt++) {
            sf[nt][0] = __expf(sf[nt][0] - nm0);
            sf[nt][1] = __expf(sf[nt][1] - nm0);
            sf[nt][2] = __expf(sf[nt][2] - nm1);
            sf[nt][3] = __expf(sf[nt][3] - nm1);
            rs0 += sf[nt][0] + sf[nt][1];
            rs1 += sf[nt][2] + sf[nt][3];
        }
        rs0 += __shfl_xor_sync(0xFFFFFFFF, rs0, 1);
        rs0 += __shfl_xor_sync(0xFFFFFFFF, rs0, 2);
        rs1 += __shfl_xor_sync(0xFFFFFFFF, rs1, 1);
        rs1 += __shfl_xor_sync(0xFFFFFFFF, rs1, 2);
        lrow0 = lrow0 * al0 + rs0;
        lrow1 = lrow1 * al1 + rs1;

        #pragma unroll
        for (int nt = 0; nt < 16; nt++) {
            of[nt][0] *= al0; of[nt][1] *= al0;
            of[nt][2] *= al1; of[nt][3] *= al1;
        }

        #pragma unroll
        for (int kt = 0; kt < 4; kt++) {
            uint32_t a[4];
            a[0] = pack_f16(sf[2 * kt][0],     sf[2 * kt][1]);
            a[1] = pack_f16(sf[2 * kt][2],     sf[2 * kt][3]);
            a[2] = pack_f16(sf[2 * kt + 1][0], sf[2 * kt + 1][1]);
            a[3] = pack_f16(sf[2 * kt + 1][2], sf[2 * kt + 1][3]);
            const int vrow = kt * 16 + ((lane >> 3) & 1) * 8 + (lane & 7);
            #pragma unroll
            for (int nb = 0; nb < 8; nb++) {
                uint32_t b[4];
                ldsm4t(b, st + 16384 + swz256(vrow, nb * 2 + ((lane >> 4) & 1)));
                mma_f16(of[nb * 2 + 0], a, b[0], b[1]);
                mma_f16(of[nb * 2 + 1], a, b[2], b[3]);
            }
        }
        // no trailing sync: next iteration's issue targets the slot whose
        // reads completed before this iteration's top barrier.
        slot  = (slot  == 2) ? 0 : slot + 1;
        slot2 = (slot2 == 2) ? 0 : slot2 + 1;
    }

    const float inv0 = 1.f / lrow0;
    const float inv1 = 1.f / lrow1;
    const int b = bh >> 4, h = bh & 15;
    const int r0 = m0 + wid * 16 + (lane >> 2);
    #pragma unroll
    for (int nt = 0; nt < 16; nt++) {
        const int gc = h * HD + nt * 8 + (lane & 3) * 2;
        *(__half2*)(O16 + (size_t)(b * S_LEN + r0) * DIM + gc) =
            __floats2half2_rn(of[nt][0] * inv0, of[nt][1] * inv0);
        *(__half2*)(O16 + (size_t)(b * S_LEN + r0 + 8) * DIM + gc) =
            __floats2half2_rn(of[nt][2] * inv1, of[nt][3] * inv1);
    }
}

// ---------------- launch ----------------
extern "C" void kernel_launch(void* const* d_in, const int* in_sizes, int n_in,
                              void* d_out, int out_size)
{
    const float* x          = (const float*)d_in[0];
    const float* k_cache    = (const float*)d_in[1];
    const float* v_cache    = (const float*)d_in[2];
    const float* attn_norm_w= (const float*)d_in[3];
    const float* ffn_norm_w = (const float*)d_in[4];
    const float* wq = (const float*)d_in[5];
    const float* bq = (const float*)d_in[6];
    const float* wk = (const float*)d_in[7];
    const float* bk = (const float*)d_in[8];
    const float* wv = (const float*)d_in[9];
    const float* bv = (const float*)d_in[10];
    const float* wo = (const float*)d_in[11];
    const float* bo = (const float*)d_in[12];
    const float* w_gate = (const float*)d_in[13];
    const float* b_gate = (const float*)d_in[14];
    const float* w_val  = (const float*)d_in[15];
    const float* b_val  = (const float*)d_in[16];
    const float* w_proj = (const float*)d_in[17];
    const float* b_proj = (const float*)d_in[18];
    const float* fcos   = (const float*)d_in[19];
    const float* fsin   = (const float*)d_in[20];

    float* out_x = (float*)d_out;
    float* out_k = out_x + OUT_X_ELEMS;
    float* out_v = out_k + OUT_KV_ELEMS;

    float *p_x1;
    __half *p_hA16, *p_h216, *p_o16, *p_gt16;
    __half *p_q16, *p_k16, *p_v16;
    __half *p_wqkv, *p_wo, *p_wg, *p_wv2, *p_wp;

    cudaGetSymbolAddress((void**)&p_x1, g_x1);
    cudaGetSymbolAddress((void**)&p_hA16, g_hA16);
    cudaGetSymbolAddress((void**)&p_h216, g_h216);
    cudaGetSymbolAddress((void**)&p_o16,  g_o16);
    cudaGetSymbolAddress((void**)&p_gt16, g_gt16);
    cudaGetSymbolAddress((void**)&p_q16,  g_q16);
    cudaGetSymbolAddress((void**)&p_k16,  g_k16);
    cudaGetSymbolAddress((void**)&p_v16,  g_v16);
    cudaGetSymbolAddress((void**)&p_wqkv, g_wqkv);
    cudaGetSymbolAddress((void**)&p_wo,   g_wo);
    cudaGetSymbolAddress((void**)&p_wg,   g_wg);
    cudaGetSymbolAddress((void**)&p_wv2,  g_wv2);
    cudaGetSymbolAddress((void**)&p_wp,   g_wp);

    cudaFuncSetAttribute(gemm_mma<1>, cudaFuncAttributeMaxDynamicSharedMemorySize, GM_SMEM);
    cudaFuncSetAttribute(gemm_qkv,   cudaFuncAttributeMaxDynamicSharedMemorySize, GM_SMEM);
    cudaFuncSetAttribute(gemm_ffn,   cudaFuncAttributeMaxDynamicSharedMemorySize, GM_SMEM);
    cudaFuncSetAttribute(flash_mma,  cudaFuncAttributeMaxDynamicSharedMemorySize, F_SMEM);

    // ---- weight conversion + transpose ----
    weight_conv4<<<dim3(64, 16, 4), 256>>>(
        wq, wk, wv, wo,
        p_wqkv, p_wqkv + DIM * DIM, p_wqkv + 2 * DIM * DIM, p_wo, DIM, DIM);
    weight_conv2<<<dim3(64, 64, 2), 256>>>(w_gate, w_val, p_wg, p_wv2, FF_DIM, DIM);
    weight_conv1<<<dim3(256, 16), 256>>>(w_proj, p_wp, DIM, FF_DIM);

    // ---- attention block ----
    rmsnorm_h<<<ROWS, 256>>>(x, attn_norm_w, p_hA16);
    gemm_qkv<<<dim3(24, 32), 256, GM_SMEM>>>(
        p_hA16, p_wqkv, bq, bk, bv, fcos, fsin,
        out_k, out_v, p_q16, p_k16, p_v16);

    copy_cache<<<4096, 256>>>(k_cache, out_k, p_k16);
    copy_cache<<<4096, 256>>>(v_cache, out_v, p_v16);

    flash_mma<<<dim3(S_LEN / FBM, BATCH * HEADS), 256, F_SMEM>>>(
        p_q16, p_k16, p_v16, p_o16);

    gemm_mma<1><<<dim3(8, 32), 256, GM_SMEM>>>(
        p_o16, p_wo, bo, x, p_x1, nullptr, ROWS, DIM, DIM);

    // ---- ffn block ----
    rmsnorm_h<<<ROWS, 256>>>(p_x1, ffn_norm_w, p_h216);
    gemm_ffn<<<dim3(64, 32), 256, GM_SMEM>>>(
        p_h216, p_wg, p_wv2, b_gate, b_val, p_gt16);
    gemm_mma<1><<<dim3(8, 32), 256, GM_SMEM>>>(
        p_gt16, p_wp, b_proj, p_x1, out_x, nullptr, ROWS, DIM, FF_DIM);
}